// round 1
// baseline (speedup 1.0000x reference)
#include <cuda_runtime.h>
#include <cuda_bf16.h>
#include <math.h>

// Problem constants
#define LL 6
#define HH 8
#define CC 512
#define DD 64
#define FF 2048
#define VV 32000
#define BB 2
#define TT 1024
#define M2 (BB*TT)          // 2048 token rows
#define BH (BB*HH)          // 16 attention batches

// ---------------------------------------------------------------------------
// Scratch (static device globals — allocation-free per harness rules)
// ---------------------------------------------------------------------------
__device__ float g_enc[M2*CC];        // encoder activations / enc_out
__device__ float g_dec[M2*CC];        // decoder activations
__device__ float g_ln [M2*CC];        // layernorm output
__device__ float g_q  [BH*TT*DD];
__device__ float g_k  [BH*TT*DD];
__device__ float g_v  [BH*TT*DD];
__device__ float g_s  [(long)BH*TT*TT];  // attention scores (64 MB)
__device__ float g_att[M2*CC];        // attention head-concat output
__device__ float g_ffn[M2*FF];        // ffn hidden

// ---------------------------------------------------------------------------
// Generic tiled SGEMM.
//  C[z] = alpha * A[z] @ B[z] (+ bias) (+ resid) (relu?)
//  A row-major [M,K] lda, B row-major [K,N] ldb (or [N,K] if TRANSB), C [M,N] ldc.
//  Per-z offsets: off = (z/zInner)*Out + (z%zInner)*In.
//  resid/bias share C's z-offsets / col indexing.
// ---------------------------------------------------------------------------
template<int BM,int BN,int BK,int TM,int TN,bool TRANSB>
__global__ __launch_bounds__(256)
void gemm_k(const float* __restrict__ A, const float* __restrict__ B,
            float* __restrict__ C, const float* __restrict__ bias,
            const float* __restrict__ resid,
            int M, int N, int K, int lda, int ldb, int ldc,
            int zInner, long aOut, long aIn, long bOut, long bIn,
            long cOut, long cIn, long biasIn, float alpha, int relu)
{
    int z = blockIdx.z;
    int zo = z / zInner, zi = z % zInner;
    A += zo*aOut + zi*aIn;
    B += zo*bOut + zi*bIn;
    long cOff = zo*cOut + zi*cIn;
    C += cOff;
    if (resid) resid += cOff;
    if (bias)  bias  += zi*biasIn;

    __shared__ float As[BK][BM];
    __shared__ float Bs[BK][BN];

    const int row0 = blockIdx.y * BM;
    const int col0 = blockIdx.x * BN;
    const int tid  = threadIdx.x;
    const int tr   = tid / (BN/TN);
    const int tc   = tid % (BN/TN);

    float acc[TM][TN];
    #pragma unroll
    for (int i=0;i<TM;i++)
        #pragma unroll
        for (int j=0;j<TN;j++) acc[i][j] = 0.f;

    for (int k0 = 0; k0 < K; k0 += BK) {
        // Load A tile (transposed into smem)
        #pragma unroll
        for (int i = tid*4; i < BM*BK; i += 256*4) {
            int r = i / BK, c = i % BK;
            float4 v4 = *(const float4*)(A + (long)(row0+r)*lda + k0 + c);
            As[c+0][r]=v4.x; As[c+1][r]=v4.y; As[c+2][r]=v4.z; As[c+3][r]=v4.w;
        }
        if (!TRANSB) {
            #pragma unroll
            for (int i = tid*4; i < BK*BN; i += 256*4) {
                int r = i / BN, c = i % BN;
                *(float4*)&Bs[r][c] = *(const float4*)(B + (long)(k0+r)*ldb + col0 + c);
            }
        } else {
            // B stored [N,K] row-major; Bs[k][n] = B[(col0+n)*ldb + k0+k]
            #pragma unroll
            for (int i = tid*4; i < BN*BK; i += 256*4) {
                int n = i / BK, c = i % BK;
                float4 v4 = *(const float4*)(B + (long)(col0+n)*ldb + k0 + c);
                Bs[c+0][n]=v4.x; Bs[c+1][n]=v4.y; Bs[c+2][n]=v4.z; Bs[c+3][n]=v4.w;
            }
        }
        __syncthreads();

        #pragma unroll
        for (int k=0;k<BK;k++) {
            float a[TM], b[TN];
            #pragma unroll
            for (int i=0;i<TM;i+=4) *(float4*)&a[i] = *(const float4*)&As[k][tr*TM+i];
            #pragma unroll
            for (int j=0;j<TN;j+=4) *(float4*)&b[j] = *(const float4*)&Bs[k][tc*TN+j];
            #pragma unroll
            for (int i=0;i<TM;i++)
                #pragma unroll
                for (int j=0;j<TN;j++)
                    acc[i][j] = fmaf(a[i], b[j], acc[i][j]);
        }
        __syncthreads();
    }

    // Epilogue
    #pragma unroll
    for (int i=0;i<TM;i++) {
        int row = row0 + tr*TM + i;
        float* crow = C + (long)row*ldc;
        const float* rrow = resid ? resid + (long)row*ldc : nullptr;
        #pragma unroll
        for (int j=0;j<TN;j+=4) {
            int col = col0 + tc*TN + j;
            float4 o;
            o.x = acc[i][j+0]*alpha; o.y = acc[i][j+1]*alpha;
            o.z = acc[i][j+2]*alpha; o.w = acc[i][j+3]*alpha;
            if (bias) {
                o.x += bias[col+0]; o.y += bias[col+1];
                o.z += bias[col+2]; o.w += bias[col+3];
            }
            if (rrow) {
                float4 r4 = *(const float4*)(rrow + col);
                o.x += r4.x; o.y += r4.y; o.z += r4.z; o.w += r4.w;
            }
            if (relu) {
                o.x = fmaxf(o.x,0.f); o.y = fmaxf(o.y,0.f);
                o.z = fmaxf(o.z,0.f); o.w = fmaxf(o.w,0.f);
            }
            *(float4*)(crow + col) = o;
        }
    }
}

// ---------------------------------------------------------------------------
// Block reductions (256 threads)
// ---------------------------------------------------------------------------
template<bool IS_MAX>
__device__ __forceinline__ float blockReduce(float v)
{
    __shared__ float sh[8];
    int lane = threadIdx.x & 31, w = threadIdx.x >> 5;
    #pragma unroll
    for (int o=16;o;o>>=1) {
        float u = __shfl_xor_sync(0xffffffffu, v, o);
        v = IS_MAX ? fmaxf(v,u) : v+u;
    }
    if (lane==0) sh[w] = v;
    __syncthreads();
    if (w==0) {
        v = (lane < 8) ? sh[lane] : (IS_MAX ? -__int_as_float(0x7f800000) : 0.f);
        #pragma unroll
        for (int o=4;o;o>>=1) {
            float u = __shfl_xor_sync(0xffffffffu, v, o);
            v = IS_MAX ? fmaxf(v,u) : v+u;
        }
        if (lane==0) sh[0] = v;
    }
    __syncthreads();
    float r = sh[0];
    __syncthreads();
    return r;
}

// ---------------------------------------------------------------------------
// Softmax over rows of [BH, T, T]; causal masks s>t to 0 after normalize.
// ---------------------------------------------------------------------------
__global__ __launch_bounds__(256)
void softmax_k(float* __restrict__ s, int causal)
{
    long row = blockIdx.x;
    int t = (int)(row % TT);
    float* p = s + row * (long)TT;
    int n = causal ? (t+1) : TT;
    int tid = threadIdx.x;

    float mx = -__int_as_float(0x7f800000);
    for (int i=tid; i<n; i+=256) mx = fmaxf(mx, p[i]);
    mx = blockReduce<true>(mx);

    float sum = 0.f;
    for (int i=tid; i<n; i+=256) {
        float e = __expf(p[i] - mx);
        p[i] = e;
        sum += e;
    }
    sum = blockReduce<false>(sum);
    float inv = 1.f / sum;
    for (int i=tid; i<TT; i+=256) p[i] = (i<n) ? p[i]*inv : 0.f;
}

// ---------------------------------------------------------------------------
// LayerNorm: rows of C=512, gamma/beta pointers
// ---------------------------------------------------------------------------
__global__ __launch_bounds__(256)
void ln_k(const float* __restrict__ x, float* __restrict__ out,
          const float* __restrict__ gamma, const float* __restrict__ beta)
{
    long row = blockIdx.x;
    const float* xr = x + row*(long)CC;
    int tid = threadIdx.x;
    float v0 = xr[tid], v1 = xr[tid+256];
    float mu = blockReduce<false>(v0+v1) * (1.f/CC);
    float d0 = v0-mu, d1 = v1-mu;
    float var = blockReduce<false>(d0*d0 + d1*d1) * (1.f/CC);
    float inv = rsqrtf(var + 1e-5f);
    out[row*(long)CC + tid      ] = d0*inv*gamma[tid]     + beta[tid];
    out[row*(long)CC + tid + 256] = d1*inv*gamma[tid+256] + beta[tid+256];
}

// ---------------------------------------------------------------------------
// Embedding + positional encoding
// ---------------------------------------------------------------------------
__global__ __launch_bounds__(256)
void embed_k(const int* __restrict__ tok, const float* __restrict__ emb,
             float* __restrict__ out)
{
    long idx = (long)blockIdx.x*256 + threadIdx.x;
    if (idx >= (long)BB*TT*CC) return;
    int c = (int)(idx % CC);
    long bt = idx / CC;
    int t = (int)(bt % TT);
    int token = tok[bt];
    const int half = CC/2;
    float pe;
    if (c < half) {
        float rate = powf(10000.f, -(float)c / half);
        pe = sinf((float)t * rate);
    } else {
        float rate = powf(10000.f, -(float)(c-half) / half);
        pe = cosf((float)t * rate);
    }
    out[idx] = emb[(long)token*CC + c] * 22.62741699796952f + pe;  // sqrt(512)
}

// ---------------------------------------------------------------------------
// Host-side launchers
// ---------------------------------------------------------------------------
static void gemm_plain(const float* A, const float* Bm, float* Cm,
                       const float* bias, const float* resid,
                       int M, int N, int K, int relu, float alpha)
{
    dim3 grid(N/128, M/128, 1);
    gemm_k<128,128,16,8,8,false><<<grid,256>>>(
        A, Bm, Cm, bias, resid, M, N, K, K, N, N,
        1, 0,0,0,0,0,0, 0, alpha, relu);
}

// Full multi-head attention: out[b,t,h*D+d] written into att (head-concat).
static void attention(const float* xq, const float* xkv,
                      const float* wqkv, const float* bqkv,
                      float* q, float* k, float* v, float* s, float* att,
                      int causal)
{
    // Q/K/V projections: per (b,h): [T,C] @ [C,D] + bias
    for (int j=0;j<3;j++) {
        const float* xin = (j==0) ? xq : xkv;
        float* outp = (j==0) ? q : (j==1) ? k : v;
        dim3 grid(DD/64, TT/128, BH);
        gemm_k<128,64,16,8,4,false><<<grid,256>>>(
            xin, wqkv + (long)j*HH*CC*DD, outp,
            bqkv + (long)j*HH*DD, nullptr,
            TT, DD, CC, CC, DD, DD,
            HH, (long)TT*CC, 0, 0, (long)CC*DD,
            (long)HH*TT*DD, (long)TT*DD, DD, 1.f, 0);
    }
    // scores = q @ k^T * sqrt(D)   (faithful to reference scaling)
    {
        dim3 grid(TT/128, TT/128, BH);
        gemm_k<128,128,16,8,8,true><<<grid,256>>>(
            q, k, s, nullptr, nullptr,
            TT, TT, DD, DD, DD, TT,
            1, (long)TT*DD, 0, (long)TT*DD, 0,
            (long)TT*TT, 0, 0, 8.0f, 0);
    }
    softmax_k<<<BH*TT, 256>>>(s, causal);
    // out = p @ v, written directly at head-concat position (ldc = C, col offset h*D)
    {
        dim3 grid(DD/64, TT/128, BH);
        gemm_k<128,64,16,8,4,false><<<grid,256>>>(
            s, v, att, nullptr, nullptr,
            TT, DD, TT, TT, DD, CC,
            HH, (long)HH*TT*TT, (long)TT*TT,
            (long)HH*TT*DD, (long)TT*DD,
            (long)TT*CC, (long)DD, 0, 1.f, 0);
    }
}

extern "C" void kernel_launch(void* const* d_in, const int* in_sizes, int n_in,
                              void* d_out, int out_size)
{
    const int*   src     = (const int*)  d_in[0];
    const int*   tgt     = (const int*)  d_in[1];
    const float* src_emb = (const float*)d_in[2];
    const float* tgt_emb = (const float*)d_in[3];
    const float* e_wqkv  = (const float*)d_in[4];
    const float* e_bqkv  = (const float*)d_in[5];
    const float* e_wo    = (const float*)d_in[6];
    const float* e_bo    = (const float*)d_in[7];
    const float* e_ln1   = (const float*)d_in[8];
    const float* e_ln2   = (const float*)d_in[9];
    const float* e_fw1   = (const float*)d_in[10];
    const float* e_fb1   = (const float*)d_in[11];
    const float* e_fw2   = (const float*)d_in[12];
    const float* e_fb2   = (const float*)d_in[13];
    const float* dsw     = (const float*)d_in[14];
    const float* dsb     = (const float*)d_in[15];
    const float* dw1     = (const float*)d_in[16];
    const float* db1     = (const float*)d_in[17];
    const float* dln1    = (const float*)d_in[18];
    const float* dcw     = (const float*)d_in[19];
    const float* dcb     = (const float*)d_in[20];
    const float* dw2     = (const float*)d_in[21];
    const float* db2     = (const float*)d_in[22];
    const float* dln2    = (const float*)d_in[23];
    const float* dln3    = (const float*)d_in[24];
    const float* dfw1    = (const float*)d_in[25];
    const float* dfb1    = (const float*)d_in[26];
    const float* dfw2    = (const float*)d_in[27];
    const float* dfb2    = (const float*)d_in[28];
    const float* wf      = (const float*)d_in[29];
    const float* bf      = (const float*)d_in[30];
    float* out = (float*)d_out;

    float *gx,*gy,*gl,*gq,*gk,*gv,*gs,*ga,*gf;
    cudaGetSymbolAddress((void**)&gx, g_enc);
    cudaGetSymbolAddress((void**)&gy, g_dec);
    cudaGetSymbolAddress((void**)&gl, g_ln);
    cudaGetSymbolAddress((void**)&gq, g_q);
    cudaGetSymbolAddress((void**)&gk, g_k);
    cudaGetSymbolAddress((void**)&gv, g_v);
    cudaGetSymbolAddress((void**)&gs, g_s);
    cudaGetSymbolAddress((void**)&ga, g_att);
    cudaGetSymbolAddress((void**)&gf, g_ffn);

    const int embBlocks = (int)(((long)BB*TT*CC + 255) / 256);

    // ---------------- Encoder ----------------
    embed_k<<<embBlocks,256>>>(src, src_emb, gx);
    for (int l=0; l<LL; l++) {
        const float* ln1g = e_ln1 + (long)l*2*CC;
        ln_k<<<M2,256>>>(gx, gl, ln1g, ln1g + CC);
        attention(gl, gl,
                  e_wqkv + (long)l*3*HH*CC*DD, e_bqkv + (long)l*3*HH*DD,
                  gq, gk, gv, gs, ga, 0);
        gemm_plain(ga, e_wo + (long)l*CC*CC, gx, e_bo + (long)l*CC, gx,
                   M2, CC, CC, 0, 1.f);
        const float* ln2g = e_ln2 + (long)l*2*CC;
        ln_k<<<M2,256>>>(gx, gl, ln2g, ln2g + CC);
        gemm_plain(gl, e_fw1 + (long)l*CC*FF, gf, e_fb1 + (long)l*FF, nullptr,
                   M2, FF, CC, 1, 1.f);
        gemm_plain(gf, e_fw2 + (long)l*FF*CC, gx, e_fb2 + (long)l*CC, gx,
                   M2, CC, FF, 0, 1.f);
    }

    // ---------------- Decoder ----------------
    embed_k<<<embBlocks,256>>>(tgt, tgt_emb, gy);
    for (int l=0; l<LL; l++) {
        const float* l1 = dln1 + (long)l*2*CC;
        ln_k<<<M2,256>>>(gy, gl, l1, l1 + CC);
        attention(gl, gl,
                  dsw + (long)l*3*HH*CC*DD, dsb + (long)l*3*HH*DD,
                  gq, gk, gv, gs, ga, 1);                      // causal
        gemm_plain(ga, dw1 + (long)l*CC*CC, gy, db1 + (long)l*CC, gy,
                   M2, CC, CC, 0, 1.f);
        const float* l2 = dln2 + (long)l*2*CC;
        ln_k<<<M2,256>>>(gy, gl, l2, l2 + CC);
        attention(gl, gx,                                      // cross: kv = enc_out
                  dcw + (long)l*3*HH*CC*DD, dcb + (long)l*3*HH*DD,
                  gq, gk, gv, gs, ga, 0);
        gemm_plain(ga, dw2 + (long)l*CC*CC, gy, db2 + (long)l*CC, gy,
                   M2, CC, CC, 0, 1.f);
        const float* l3 = dln3 + (long)l*2*CC;
        ln_k<<<M2,256>>>(gy, gl, l3, l3 + CC);
        gemm_plain(gl, dfw1 + (long)l*CC*FF, gf, dfb1 + (long)l*FF, nullptr,
                   M2, FF, CC, 1, 1.f);
        gemm_plain(gf, dfw2 + (long)l*FF*CC, gy, dfb2 + (long)l*CC, gy,
                   M2, CC, FF, 0, 1.f);
    }

    // ---------------- Final logits ----------------
    gemm_plain(gy, wf, out, bf, nullptr, M2, VV, CC, 0, 1.f);
}

// round 3
// speedup vs baseline: 1.1004x; 1.1004x over previous
#include <cuda_runtime.h>
#include <cuda_bf16.h>
#include <math.h>
#include <stdint.h>

// Problem constants
#define LL 6
#define HH 8
#define CC 512
#define DD 64
#define FF 2048
#define VV 32000
#define BB 2
#define TT 1024
#define M2 (BB*TT)          // 2048 token rows
#define BH (BB*HH)          // 16 attention batches
#define QSZ (BH*TT*DD)      // one of Q/K/V

// ---------------------------------------------------------------------------
// Scratch (static device globals — allocation-free per harness rules)
// ---------------------------------------------------------------------------
__device__ float g_enc[M2*CC];
__device__ float g_dec[M2*CC];
__device__ float g_ln [M2*CC];
__device__ float g_qkv[3*QSZ];           // [j][b][h][T][D]
__device__ float g_s  [(long)BH*TT*TT];  // attention scores (64 MB)
__device__ float g_att[M2*CC];
__device__ float g_ffn[M2*FF];

// ---------------------------------------------------------------------------
// TF32 tensor-core helpers (3xTF32 fp32-emulation)
// ---------------------------------------------------------------------------
__device__ __forceinline__ uint32_t f2tf(float f){
    uint32_t r; asm("cvt.rna.tf32.f32 %0, %1;" : "=r"(r) : "f"(f)); return r;
}
__device__ __forceinline__ void split_tf(float v, uint32_t& hi, uint32_t& lo){
    hi = f2tf(v);
    lo = f2tf(v - __uint_as_float(hi));
}
__device__ __forceinline__ void cp16(void* dst, const void* src){
    uint32_t s = (uint32_t)__cvta_generic_to_shared(dst);
    asm volatile("cp.async.cg.shared.global [%0], [%1], 16;" :: "r"(s), "l"(src));
}
__device__ __forceinline__ void mma8(float* c, const uint32_t* a, const uint32_t* b){
    asm volatile("mma.sync.aligned.m16n8k8.row.col.f32.tf32.tf32.f32 "
        "{%0,%1,%2,%3},{%4,%5,%6,%7},{%8,%9},{%0,%1,%2,%3};"
        : "+f"(c[0]),"+f"(c[1]),"+f"(c[2]),"+f"(c[3])
        : "r"(a[0]),"r"(a[1]),"r"(a[2]),"r"(a[3]),"r"(b[0]),"r"(b[1]));
}

// ---------------------------------------------------------------------------
// Generic batched 3xTF32 GEMM (fp32-accurate).
//  z decomposed: i0 = z/zDiv1; rem = z%zDiv1; i1 = rem/zDiv2; i2 = rem%zDiv2
//  A pointer = (i0==0 ? A : A2) + i0*aS0 + i1*aS1 + i2*aS2  (QKV fusion trick)
//  B row-major [K,N] (or [N,K] when TRANSB).
//  C = alpha*A@B (+bias) (+resid) (relu?)
// ---------------------------------------------------------------------------
template<int BM,int BN,int BK,int WM,int WN,bool TRANSB>
__global__ __launch_bounds__(256)
void mma_gemm(const float* __restrict__ A, const float* __restrict__ A2,
              const float* __restrict__ B, float* __restrict__ C,
              const float* __restrict__ bias, const float* __restrict__ resid,
              int K, int lda, int ldb, int ldc,
              int zDiv1, int zDiv2,
              long aS0, long aS1, long aS2,
              long bS0, long bS1, long bS2,
              long cS0, long cS1, long cS2,
              long sS0, long sS1, long sS2,
              float alpha, int relu)
{
    constexpr int BKP = BK + 4;     // smem pad: conflict-free A frag loads
    constexpr int BNP = BN + 8;     // smem pad: conflict-free B frag loads
    constexpr int WCOLS = BN / WN;
    constexpr int MITER = WM/16, NITER = WN/8;

    const int z = blockIdx.z;
    const int i0 = z / zDiv1, rem = z % zDiv1;
    const int i1 = rem / zDiv2, i2 = rem % zDiv2;
    const float* Ap = ((i0==0) ? A : A2) + i0*aS0 + i1*aS1 + i2*aS2;
    const float* Bp = B + i0*bS0 + i1*bS1 + i2*bS2;
    const long cOff = i0*cS0 + i1*cS1 + i2*cS2;
    float* Cp = C + cOff;
    const float* Rp = resid ? resid + cOff : nullptr;
    const float* bp = bias ? bias + i0*sS0 + i1*sS1 + i2*sS2 : nullptr;

    const int row0 = blockIdx.y * BM;
    const int col0 = blockIdx.x * BN;
    const int tid  = threadIdx.x;
    const int lane = tid & 31, w = tid >> 5;
    const int wr = w / WCOLS, wc = w % WCOLS;

    __shared__ float As[2][BM][BKP];
    __shared__ float Bs[2][BK][BNP];

    float acc[MITER][NITER][4];
    #pragma unroll
    for (int mi=0;mi<MITER;mi++)
        #pragma unroll
        for (int ni=0;ni<NITER;ni++)
            #pragma unroll
            for (int q=0;q<4;q++) acc[mi][ni][q] = 0.f;

    auto loadA = [&](int buf, int k0){
        #pragma unroll
        for (int i=0;i<(BM*BK/4)/256;i++){
            int id = tid + i*256;
            int r = id / (BK/4), c = (id % (BK/4))*4;
            cp16(&As[buf][r][c], Ap + (long)(row0+r)*lda + k0 + c);
        }
    };
    auto loadB = [&](int buf, int k0){
        #pragma unroll
        for (int i=0;i<(BK*BN/4)/256;i++){
            int id = tid + i*256;
            int r = id / (BN/4), c = (id % (BN/4))*4;
            cp16(&Bs[buf][r][c], Bp + (long)(k0+r)*ldb + col0 + c);
        }
    };
    auto loadBT = [&](int buf, int k0){
        #pragma unroll
        for (int i=0;i<(BN*BK/4)/256;i++){
            int id = tid + i*256;
            int n = id / (BK/4), c = (id % (BK/4))*4;
            float4 v = *(const float4*)(Bp + (long)(col0+n)*ldb + k0 + c);
            Bs[buf][c+0][n]=v.x; Bs[buf][c+1][n]=v.y;
            Bs[buf][c+2][n]=v.z; Bs[buf][c+3][n]=v.w;
        }
    };
    auto compute = [&](int buf){
        #pragma unroll
        for (int kk=0; kk<BK; kk+=8){
            uint32_t aHi[MITER][4], aLo[MITER][4];
            uint32_t bHi[NITER][2], bLo[NITER][2];
            const int kb = kk + (lane&3);
            #pragma unroll
            for (int mi=0; mi<MITER; mi++){
                int m = wr*WM + mi*16 + (lane>>2);
                split_tf(As[buf][m  ][kb  ], aHi[mi][0], aLo[mi][0]);
                split_tf(As[buf][m+8][kb  ], aHi[mi][1], aLo[mi][1]);
                split_tf(As[buf][m  ][kb+4], aHi[mi][2], aLo[mi][2]);
                split_tf(As[buf][m+8][kb+4], aHi[mi][3], aLo[mi][3]);
            }
            #pragma unroll
            for (int ni=0; ni<NITER; ni++){
                int n = wc*WN + ni*8 + (lane>>2);
                split_tf(Bs[buf][kb  ][n], bHi[ni][0], bLo[ni][0]);
                split_tf(Bs[buf][kb+4][n], bHi[ni][1], bLo[ni][1]);
            }
            #pragma unroll
            for (int mi=0; mi<MITER; mi++)
                #pragma unroll
                for (int ni=0; ni<NITER; ni++){
                    mma8(acc[mi][ni], aLo[mi], bHi[ni]);
                    mma8(acc[mi][ni], aHi[mi], bLo[ni]);
                    mma8(acc[mi][ni], aHi[mi], bHi[ni]);
                }
        }
    };

    if (!TRANSB){
        loadA(0,0); loadB(0,0);
        asm volatile("cp.async.commit_group;");
        const int nIter = K/BK;
        int buf = 0;
        for (int it=0; it<nIter; ++it){
            if (it+1<nIter){
                loadA(buf^1,(it+1)*BK); loadB(buf^1,(it+1)*BK);
                asm volatile("cp.async.commit_group;");
                asm volatile("cp.async.wait_group 1;");
            } else {
                asm volatile("cp.async.wait_group 0;");
            }
            __syncthreads();
            compute(buf);
            __syncthreads();
            buf ^= 1;
        }
    } else {
        for (int k0=0; k0<K; k0+=BK){
            if (k0) __syncthreads();
            loadA(0,k0);
            asm volatile("cp.async.commit_group;");
            loadBT(0,k0);
            asm volatile("cp.async.wait_group 0;");
            __syncthreads();
            compute(0);
        }
    }

    // Epilogue
    #pragma unroll
    for (int mi=0;mi<MITER;mi++){
        #pragma unroll
        for (int ni=0;ni<NITER;ni++){
            int r  = row0 + wr*WM + mi*16 + (lane>>2);
            int cl = col0 + wc*WN + ni*8 + 2*(lane&3);
            #pragma unroll
            for (int h=0; h<2; h++){
                int rr = r + 8*h;
                float x = acc[mi][ni][2*h  ]*alpha;
                float y = acc[mi][ni][2*h+1]*alpha;
                if (bp){ x += bp[cl]; y += bp[cl+1]; }
                if (Rp){ float2 t = *(const float2*)(Rp + (long)rr*ldc + cl);
                         x += t.x; y += t.y; }
                if (relu){ x = fmaxf(x,0.f); y = fmaxf(y,0.f); }
                *(float2*)(Cp + (long)rr*ldc + cl) = make_float2(x,y);
            }
        }
    }
}

// ---------------------------------------------------------------------------
// Block reductions (256 threads)
// ---------------------------------------------------------------------------
template<bool IS_MAX>
__device__ __forceinline__ float blockReduce(float v)
{
    __shared__ float sh[8];
    int lane = threadIdx.x & 31, w = threadIdx.x >> 5;
    #pragma unroll
    for (int o=16;o;o>>=1) {
        float u = __shfl_xor_sync(0xffffffffu, v, o);
        v = IS_MAX ? fmaxf(v,u) : v+u;
    }
    if (lane==0) sh[w] = v;
    __syncthreads();
    if (w==0) {
        v = (lane < 8) ? sh[lane] : (IS_MAX ? -__int_as_float(0x7f800000) : 0.f);
        #pragma unroll
        for (int o=4;o;o>>=1) {
            float u = __shfl_xor_sync(0xffffffffu, v, o);
            v = IS_MAX ? fmaxf(v,u) : v+u;
        }
        if (lane==0) sh[0] = v;
    }
    __syncthreads();
    float r = sh[0];
    __syncthreads();
    return r;
}

// ---------------------------------------------------------------------------
// Softmax over rows of [BH, T, T]; causal masks s>t to 0 after normalize.
// ---------------------------------------------------------------------------
__global__ __launch_bounds__(256)
void softmax_k(float* __restrict__ s, int causal)
{
    long row = blockIdx.x;
    int t = (int)(row % TT);
    float* p = s + row * (long)TT;
    int n = causal ? (t+1) : TT;
    int tid = threadIdx.x;

    float mx = -__int_as_float(0x7f800000);
    for (int i=tid; i<n; i+=256) mx = fmaxf(mx, p[i]);
    mx = blockReduce<true>(mx);

    float sum = 0.f;
    for (int i=tid; i<n; i+=256) {
        float e = __expf(p[i] - mx);
        p[i] = e;
        sum += e;
    }
    sum = blockReduce<false>(sum);
    float inv = 1.f / sum;
    for (int i=tid; i<TT; i+=256) p[i] = (i<n) ? p[i]*inv : 0.f;
}

// ---------------------------------------------------------------------------
// LayerNorm: rows of C=512
// ---------------------------------------------------------------------------
__global__ __launch_bounds__(256)
void ln_k(const float* __restrict__ x, float* __restrict__ out,
          const float* __restrict__ gamma, const float* __restrict__ beta)
{
    long row = blockIdx.x;
    const float* xr = x + row*(long)CC;
    int tid = threadIdx.x;
    float v0 = xr[tid], v1 = xr[tid+256];
    float mu = blockReduce<false>(v0+v1) * (1.f/CC);
    float d0 = v0-mu, d1 = v1-mu;
    float var = blockReduce<false>(d0*d0 + d1*d1) * (1.f/CC);
    float inv = rsqrtf(var + 1e-5f);
    out[row*(long)CC + tid      ] = d0*inv*gamma[tid]     + beta[tid];
    out[row*(long)CC + tid + 256] = d1*inv*gamma[tid+256] + beta[tid+256];
}

// ---------------------------------------------------------------------------
// Embedding + positional encoding
// ---------------------------------------------------------------------------
__global__ __launch_bounds__(256)
void embed_k(const int* __restrict__ tok, const float* __restrict__ emb,
             float* __restrict__ out)
{
    long idx = (long)blockIdx.x*256 + threadIdx.x;
    if (idx >= (long)BB*TT*CC) return;
    int c = (int)(idx % CC);
    long bt = idx / CC;
    int t = (int)(bt % TT);
    int token = tok[bt];
    const int half = CC/2;
    float pe;
    if (c < half) {
        float rate = powf(10000.f, -(float)c / half);
        pe = sinf((float)t * rate);
    } else {
        float rate = powf(10000.f, -(float)(c-half) / half);
        pe = cosf((float)t * rate);
    }
    out[idx] = emb[(long)token*CC + c] * 22.62741699796952f + pe;  // sqrt(512)
}

// ---------------------------------------------------------------------------
// Host-side launchers
// ---------------------------------------------------------------------------
static void gemmP(const float* A, const float* B, float* C,
                  const float* bias, const float* resid,
                  int M, int N, int K, int relu)
{
    if (N >= 1024) {
        dim3 g(N/128, M/128, 1);
        mma_gemm<128,128,16,64,32,false><<<g,256>>>(
            A, A, B, C, bias, resid, K, K, N, N,
            1,1, 0,0,0, 0,0,0, 0,0,0, 0,0,0, 1.f, relu);
    } else {
        dim3 g(N/64, M/128, 1);
        mma_gemm<128,64,16,32,32,false><<<g,256>>>(
            A, A, B, C, bias, resid, K, K, N, N,
            1,1, 0,0,0, 0,0,0, 0,0,0, 0,0,0, 1.f, relu);
    }
}

// Full multi-head attention; att gets head-concat output [B*T, C].
static void attention(const float* xq, const float* xkv,
                      const float* wqkv, const float* bqkv,
                      float* qkv, float* s, float* att, int causal)
{
    // Fused QKV projection: z = j*16 + b*8 + h   (j selects A vs A2)
    {
        dim3 g(1, TT/128, 48);
        mma_gemm<128,64,16,32,32,false><<<g,256>>>(
            xq, xkv, wqkv, qkv, bqkv, nullptr,
            CC, CC, DD, DD,
            16, 8,
            0, (long)TT*CC, 0,                         // A: b stride
            (long)HH*CC*DD, 0, (long)CC*DD,            // B: j, h strides
            (long)QSZ, (long)HH*TT*DD, (long)TT*DD,    // C: j, b, h
            (long)HH*DD, 0, (long)DD,                  // bias: j, h
            1.f, 0);
    }
    // scores = Q @ K^T * sqrt(D)   (z = b*H+h)
    {
        dim3 g(TT/128, TT/128, BH);
        mma_gemm<128,128,16,64,32,true><<<g,256>>>(
            qkv, qkv, qkv + QSZ, s, nullptr, nullptr,
            DD, DD, DD, TT,
            1000000, 1,
            0, (long)TT*DD, 0,
            0, (long)TT*DD, 0,
            0, (long)TT*TT, 0,
            0,0,0,
            8.0f, 0);
    }
    softmax_k<<<BH*TT, 256>>>(s, causal);
    // out = P @ V, written at head-concat position (ldc = C, col offset h*D)
    {
        dim3 g(1, TT/128, BH);
        mma_gemm<128,64,16,32,32,false><<<g,256>>>(
            s, s, qkv + 2*QSZ, att, nullptr, nullptr,
            TT, TT, DD, CC,
            1000000, HH,
            0, (long)HH*TT*TT, (long)TT*TT,
            0, (long)HH*TT*DD, (long)TT*DD,
            0, (long)TT*CC, (long)DD,
            0,0,0,
            1.f, 0);
    }
}

extern "C" void kernel_launch(void* const* d_in, const int* in_sizes, int n_in,
                              void* d_out, int out_size)
{
    const int*   src     = (const int*)  d_in[0];
    const int*   tgt     = (const int*)  d_in[1];
    const float* src_emb = (const float*)d_in[2];
    const float* tgt_emb = (const float*)d_in[3];
    const float* e_wqkv  = (const float*)d_in[4];
    const float* e_bqkv  = (const float*)d_in[5];
    const float* e_wo    = (const float*)d_in[6];
    const float* e_bo    = (const float*)d_in[7];
    const float* e_ln1   = (const float*)d_in[8];
    const float* e_ln2   = (const float*)d_in[9];
    const float* e_fw1   = (const float*)d_in[10];
    const float* e_fb1   = (const float*)d_in[11];
    const float* e_fw2   = (const float*)d_in[12];
    const float* e_fb2   = (const float*)d_in[13];
    const float* dsw     = (const float*)d_in[14];
    const float* dsb     = (const float*)d_in[15];
    const float* dw1     = (const float*)d_in[16];
    const float* db1     = (const float*)d_in[17];
    const float* dln1    = (const float*)d_in[18];
    const float* dcw     = (const float*)d_in[19];
    const float* dcb     = (const float*)d_in[20];
    const float* dw2     = (const float*)d_in[21];
    const float* db2     = (const float*)d_in[22];
    const float* dln2    = (const float*)d_in[23];
    const float* dln3    = (const float*)d_in[24];
    const float* dfw1    = (const float*)d_in[25];
    const float* dfb1    = (const float*)d_in[26];
    const float* dfw2    = (const float*)d_in[27];
    const float* dfb2    = (const float*)d_in[28];
    const float* wf      = (const float*)d_in[29];
    const float* bf      = (const float*)d_in[30];
    float* out = (float*)d_out;

    float *gx,*gy,*gl,*gq,*gs,*ga,*gf;
    cudaGetSymbolAddress((void**)&gx, g_enc);
    cudaGetSymbolAddress((void**)&gy, g_dec);
    cudaGetSymbolAddress((void**)&gl, g_ln);
    cudaGetSymbolAddress((void**)&gq, g_qkv);
    cudaGetSymbolAddress((void**)&gs, g_s);
    cudaGetSymbolAddress((void**)&ga, g_att);
    cudaGetSymbolAddress((void**)&gf, g_ffn);

    const int embBlocks = (int)(((long)BB*TT*CC + 255) / 256);

    // ---------------- Encoder ----------------
    embed_k<<<embBlocks,256>>>(src, src_emb, gx);
    for (int l=0; l<LL; l++) {
        const float* ln1g = e_ln1 + (long)l*2*CC;
        ln_k<<<M2,256>>>(gx, gl, ln1g, ln1g + CC);
        attention(gl, gl,
                  e_wqkv + (long)l*3*HH*CC*DD, e_bqkv + (long)l*3*HH*DD,
                  gq, gs, ga, 0);
        gemmP(ga, e_wo + (long)l*CC*CC, gx, e_bo + (long)l*CC, gx, M2, CC, CC, 0);
        const float* ln2g = e_ln2 + (long)l*2*CC;
        ln_k<<<M2,256>>>(gx, gl, ln2g, ln2g + CC);
        gemmP(gl, e_fw1 + (long)l*CC*FF, gf, e_fb1 + (long)l*FF, nullptr, M2, FF, CC, 1);
        gemmP(gf, e_fw2 + (long)l*FF*CC, gx, e_fb2 + (long)l*CC, gx, M2, CC, FF, 0);
    }

    // ---------------- Decoder ----------------
    embed_k<<<embBlocks,256>>>(tgt, tgt_emb, gy);
    for (int l=0; l<LL; l++) {
        const float* l1 = dln1 + (long)l*2*CC;
        ln_k<<<M2,256>>>(gy, gl, l1, l1 + CC);
        attention(gl, gl,
                  dsw + (long)l*3*HH*CC*DD, dsb + (long)l*3*HH*DD,
                  gq, gs, ga, 1);                      // causal
        gemmP(ga, dw1 + (long)l*CC*CC, gy, db1 + (long)l*CC, gy, M2, CC, CC, 0);
        const float* l2 = dln2 + (long)l*2*CC;
        ln_k<<<M2,256>>>(gy, gl, l2, l2 + CC);
        attention(gl, gx,                              // cross: kv = enc_out
                  dcw + (long)l*3*HH*CC*DD, dcb + (long)l*3*HH*DD,
                  gq, gs, ga, 0);
        gemmP(ga, dw2 + (long)l*CC*CC, gy, db2 + (long)l*CC, gy, M2, CC, CC, 0);
        const float* l3 = dln3 + (long)l*2*CC;
        ln_k<<<M2,256>>>(gy, gl, l3, l3 + CC);
        gemmP(gl, dfw1 + (long)l*CC*FF, gf, dfb1 + (long)l*FF, nullptr, M2, FF, CC, 1);
        gemmP(gf, dfw2 + (long)l*FF*CC, gy, dfb2 + (long)l*CC, gy, M2, CC, FF, 0);
    }

    // ---------------- Final logits ----------------
    gemmP(gy, wf, out, bf, nullptr, M2, VV, CC, 0);
}

// round 4
// speedup vs baseline: 1.3902x; 1.2633x over previous
#include <cuda_runtime.h>
#include <cuda_bf16.h>
#include <math.h>
#include <stdint.h>

// Problem constants
#define LL 6
#define HH 8
#define CC 512
#define DD 64
#define FF 2048
#define VV 32000
#define BB 2
#define TT 1024
#define M2 (BB*TT)          // 2048 token rows
#define BH (BB*HH)          // 16 attention batches
#define QSZ (BH*TT*DD)      // one of Q/K/V

// ---------------------------------------------------------------------------
// Scratch (static device globals — allocation-free per harness rules)
// ---------------------------------------------------------------------------
__device__ float g_enc[M2*CC];
__device__ float g_dec[M2*CC];
__device__ float g_ln [M2*CC];
__device__ float g_qkv[3*QSZ];           // [j][b][h][T][D]
__device__ float g_s  [(long)BH*TT*TT];  // attention scores (64 MB)
__device__ float g_att[M2*CC];
__device__ float g_ffn[M2*FF];

// ---------------------------------------------------------------------------
// TF32 tensor-core helpers (3xTF32 fp32-emulation, pre-split at STS time)
// ---------------------------------------------------------------------------
__device__ __forceinline__ uint32_t f2tf(float f){
    uint32_t r; asm("cvt.rna.tf32.f32 %0, %1;" : "=r"(r) : "f"(f)); return r;
}
__device__ __forceinline__ uint2 split_tf(float v){
    uint32_t hi = f2tf(v);
    uint32_t lo = f2tf(v - __uint_as_float(hi));
    return make_uint2(hi, lo);
}
__device__ __forceinline__ void mma8(float* c, const uint32_t* a, const uint32_t* b){
    asm volatile("mma.sync.aligned.m16n8k8.row.col.f32.tf32.tf32.f32 "
        "{%0,%1,%2,%3},{%4,%5,%6,%7},{%8,%9},{%0,%1,%2,%3};"
        : "+f"(c[0]),"+f"(c[1]),"+f"(c[2]),"+f"(c[3])
        : "r"(a[0]),"r"(a[1]),"r"(a[2]),"r"(a[3]),"r"(b[0]),"r"(b[1]));
}

// ---------------------------------------------------------------------------
// Generic batched 3xTF32 GEMM (fp32-accurate), pre-split smem operands.
//  z decomposed: i0 = z/zDiv1; rem = z%zDiv1; i1 = rem/zDiv2; i2 = rem%zDiv2
//  A pointer = (i0==0 ? A : A2) + i0*aS0 + i1*aS1 + i2*aS2  (QKV fusion trick)
//  B row-major [K,N] (or [N,K] when TRANSB).
//  C = alpha*A@B (+bias) (+resid) (relu?)
// ---------------------------------------------------------------------------
template<int BM,int BN,int BK,int WM,int WN,bool TRANSB>
__global__ __launch_bounds__(256)
void mma_gemm(const float* __restrict__ A, const float* __restrict__ A2,
              const float* __restrict__ B, float* __restrict__ C,
              const float* __restrict__ bias, const float* __restrict__ resid,
              int K, int lda, int ldb, int ldc,
              int zDiv1, int zDiv2,
              long aS0, long aS1, long aS2,
              long bS0, long bS1, long bS2,
              long cS0, long cS1, long cS2,
              long sS0, long sS1, long sS2,
              float alpha, int relu)
{
    constexpr int BKP = BK + 4;     // uint2 row stride for A  (conflict-free reads)
    constexpr int BNP = BN + 4;     // uint2 row stride for B  (row stride ≡ 8 mod 32)
    constexpr int WCOLS = BN / WN;
    constexpr int MITER = WM/16, NITER = WN/8;
    constexpr int AREG = BM*BK/(256*4);   // float4 per thread for A tile
    constexpr int BREG = BK*BN/(256*4);   // float4 per thread for B tile

    extern __shared__ uint2 sm2[];
    uint2* As = sm2;                    // [2][BM][BKP]
    uint2* Bs = sm2 + 2*BM*BKP;         // [2][BK][BNP]

    const int z = blockIdx.z;
    const int i0 = z / zDiv1, rem = z % zDiv1;
    const int i1 = rem / zDiv2, i2 = rem % zDiv2;
    const float* Ap = ((i0==0) ? A : A2) + i0*aS0 + i1*aS1 + i2*aS2;
    const float* Bp = B + i0*bS0 + i1*bS1 + i2*bS2;
    const long cOff = i0*cS0 + i1*cS1 + i2*cS2;
    float* Cp = C + cOff;
    const float* Rp = resid ? resid + cOff : nullptr;
    const float* bp = bias ? bias + i0*sS0 + i1*sS1 + i2*sS2 : nullptr;

    const int row0 = blockIdx.y * BM;
    const int col0 = blockIdx.x * BN;
    const int tid  = threadIdx.x;
    const int lane = tid & 31, w = tid >> 5;
    const int wr = w / WCOLS, wc = w % WCOLS;

    float acc[MITER][NITER][4];
    #pragma unroll
    for (int mi=0;mi<MITER;mi++)
        #pragma unroll
        for (int ni=0;ni<NITER;ni++)
            #pragma unroll
            for (int q=0;q<4;q++) acc[mi][ni][q] = 0.f;

    float4 ra[AREG], rb[BREG];

    auto ldgA = [&](int k0){
        #pragma unroll
        for (int i=0;i<AREG;i++){
            int id = tid + i*256;
            int r = id / (BK/4), c = (id % (BK/4))*4;
            ra[i] = *(const float4*)(Ap + (long)(row0+r)*lda + k0 + c);
        }
    };
    auto stsA = [&](int buf){
        #pragma unroll
        for (int i=0;i<AREG;i++){
            int id = tid + i*256;
            int r = id / (BK/4), c = (id % (BK/4))*4;
            uint2* d = As + buf*BM*BKP + r*BKP + c;
            uint2 s0 = split_tf(ra[i].x), s1 = split_tf(ra[i].y);
            uint2 s2 = split_tf(ra[i].z), s3 = split_tf(ra[i].w);
            ((uint4*)d)[0] = make_uint4(s0.x,s0.y,s1.x,s1.y);
            ((uint4*)d)[1] = make_uint4(s2.x,s2.y,s3.x,s3.y);
        }
    };
    auto ldgB = [&](int k0){
        #pragma unroll
        for (int i=0;i<BREG;i++){
            int id = tid + i*256;
            if (!TRANSB){
                int r = id / (BN/4), c = (id % (BN/4))*4;
                rb[i] = *(const float4*)(Bp + (long)(k0+r)*ldb + col0 + c);
            } else {
                int n = id / (BK/4), c = (id % (BK/4))*4;
                rb[i] = *(const float4*)(Bp + (long)(col0+n)*ldb + k0 + c);
            }
        }
    };
    auto stsB = [&](int buf){
        #pragma unroll
        for (int i=0;i<BREG;i++){
            int id = tid + i*256;
            if (!TRANSB){
                int r = id / (BN/4), c = (id % (BN/4))*4;
                uint2* d = Bs + buf*BK*BNP + r*BNP + c;
                uint2 s0 = split_tf(rb[i].x), s1 = split_tf(rb[i].y);
                uint2 s2 = split_tf(rb[i].z), s3 = split_tf(rb[i].w);
                ((uint4*)d)[0] = make_uint4(s0.x,s0.y,s1.x,s1.y);
                ((uint4*)d)[1] = make_uint4(s2.x,s2.y,s3.x,s3.y);
            } else {
                int n = id / (BK/4), c = (id % (BK/4))*4;
                uint2* base = Bs + buf*BK*BNP;
                base[(c+0)*BNP + n] = split_tf(rb[i].x);
                base[(c+1)*BNP + n] = split_tf(rb[i].y);
                base[(c+2)*BNP + n] = split_tf(rb[i].z);
                base[(c+3)*BNP + n] = split_tf(rb[i].w);
            }
        }
    };
    auto compute = [&](int buf){
        const uint2* Ab = As + buf*BM*BKP;
        const uint2* Bb = Bs + buf*BK*BNP;
        #pragma unroll
        for (int kk=0; kk<BK; kk+=8){
            const int kb = kk + (lane&3);
            uint2 aF[MITER][4]; uint2 bF[NITER][2];
            #pragma unroll
            for (int mi=0; mi<MITER; mi++){
                int m = wr*WM + mi*16 + (lane>>2);
                aF[mi][0] = Ab[(m  )*BKP + kb  ];
                aF[mi][1] = Ab[(m+8)*BKP + kb  ];
                aF[mi][2] = Ab[(m  )*BKP + kb+4];
                aF[mi][3] = Ab[(m+8)*BKP + kb+4];
            }
            #pragma unroll
            for (int ni=0; ni<NITER; ni++){
                int n = wc*WN + ni*8 + (lane>>2);
                bF[ni][0] = Bb[(kb  )*BNP + n];
                bF[ni][1] = Bb[(kb+4)*BNP + n];
            }
            #pragma unroll
            for (int mi=0; mi<MITER; mi++){
                uint32_t ah[4] = {aF[mi][0].x, aF[mi][1].x, aF[mi][2].x, aF[mi][3].x};
                uint32_t al[4] = {aF[mi][0].y, aF[mi][1].y, aF[mi][2].y, aF[mi][3].y};
                #pragma unroll
                for (int ni=0; ni<NITER; ni++){
                    uint32_t bh[2] = {bF[ni][0].x, bF[ni][1].x};
                    uint32_t bl[2] = {bF[ni][0].y, bF[ni][1].y};
                    mma8(acc[mi][ni], al, bh);
                    mma8(acc[mi][ni], ah, bl);
                    mma8(acc[mi][ni], ah, bh);
                }
            }
        }
    };

    const int nIter = K/BK;
    ldgA(0); ldgB(0);
    stsA(0); stsB(0);
    __syncthreads();
    for (int it=0; it<nIter; ++it){
        if (it+1 < nIter){ ldgA((it+1)*BK); ldgB((it+1)*BK); }
        compute(it & 1);
        if (it+1 < nIter){ stsA((it+1)&1); stsB((it+1)&1); }
        __syncthreads();
    }

    // Epilogue
    #pragma unroll
    for (int mi=0;mi<MITER;mi++){
        #pragma unroll
        for (int ni=0;ni<NITER;ni++){
            int r  = row0 + wr*WM + mi*16 + (lane>>2);
            int cl = col0 + wc*WN + ni*8 + 2*(lane&3);
            #pragma unroll
            for (int h=0; h<2; h++){
                int rr = r + 8*h;
                float x = acc[mi][ni][2*h  ]*alpha;
                float y = acc[mi][ni][2*h+1]*alpha;
                if (bp){ x += bp[cl]; y += bp[cl+1]; }
                if (Rp){ float2 t = *(const float2*)(Rp + (long)rr*ldc + cl);
                         x += t.x; y += t.y; }
                if (relu){ x = fmaxf(x,0.f); y = fmaxf(y,0.f); }
                *(float2*)(Cp + (long)rr*ldc + cl) = make_float2(x,y);
            }
        }
    }
}

// Shared-memory byte counts per instantiation
template<int BM,int BN,int BK>
constexpr int smemBytes(){ return (2*BM*(BK+4) + 2*BK*(BN+4)) * 8; }

// ---------------------------------------------------------------------------
// Block reductions (256 threads)
// ---------------------------------------------------------------------------
template<bool IS_MAX>
__device__ __forceinline__ float blockReduce(float v)
{
    __shared__ float sh[8];
    int lane = threadIdx.x & 31, w = threadIdx.x >> 5;
    #pragma unroll
    for (int o=16;o;o>>=1) {
        float u = __shfl_xor_sync(0xffffffffu, v, o);
        v = IS_MAX ? fmaxf(v,u) : v+u;
    }
    if (lane==0) sh[w] = v;
    __syncthreads();
    if (w==0) {
        v = (lane < 8) ? sh[lane] : (IS_MAX ? -__int_as_float(0x7f800000) : 0.f);
        #pragma unroll
        for (int o=4;o;o>>=1) {
            float u = __shfl_xor_sync(0xffffffffu, v, o);
            v = IS_MAX ? fmaxf(v,u) : v+u;
        }
        if (lane==0) sh[0] = v;
    }
    __syncthreads();
    float r = sh[0];
    __syncthreads();
    return r;
}

// ---------------------------------------------------------------------------
// Softmax over rows of [BH, T, T]; causal masks s>t to 0 after normalize.
// ---------------------------------------------------------------------------
__global__ __launch_bounds__(256)
void softmax_k(float* __restrict__ s, int causal)
{
    long row = blockIdx.x;
    int t = (int)(row % TT);
    float* p = s + row * (long)TT;
    int n = causal ? (t+1) : TT;
    int tid = threadIdx.x;

    float mx = -__int_as_float(0x7f800000);
    for (int i=tid; i<n; i+=256) mx = fmaxf(mx, p[i]);
    mx = blockReduce<true>(mx);

    float sum = 0.f;
    for (int i=tid; i<n; i+=256) {
        float e = __expf(p[i] - mx);
        p[i] = e;
        sum += e;
    }
    sum = blockReduce<false>(sum);
    float inv = 1.f / sum;
    for (int i=tid; i<TT; i+=256) p[i] = (i<n) ? p[i]*inv : 0.f;
}

// ---------------------------------------------------------------------------
// LayerNorm: rows of C=512
// ---------------------------------------------------------------------------
__global__ __launch_bounds__(256)
void ln_k(const float* __restrict__ x, float* __restrict__ out,
          const float* __restrict__ gamma, const float* __restrict__ beta)
{
    long row = blockIdx.x;
    const float* xr = x + row*(long)CC;
    int tid = threadIdx.x;
    float v0 = xr[tid], v1 = xr[tid+256];
    float mu = blockReduce<false>(v0+v1) * (1.f/CC);
    float d0 = v0-mu, d1 = v1-mu;
    float var = blockReduce<false>(d0*d0 + d1*d1) * (1.f/CC);
    float inv = rsqrtf(var + 1e-5f);
    out[row*(long)CC + tid      ] = d0*inv*gamma[tid]     + beta[tid];
    out[row*(long)CC + tid + 256] = d1*inv*gamma[tid+256] + beta[tid+256];
}

// ---------------------------------------------------------------------------
// Embedding + positional encoding
// ---------------------------------------------------------------------------
__global__ __launch_bounds__(256)
void embed_k(const int* __restrict__ tok, const float* __restrict__ emb,
             float* __restrict__ out)
{
    long idx = (long)blockIdx.x*256 + threadIdx.x;
    if (idx >= (long)BB*TT*CC) return;
    int c = (int)(idx % CC);
    long bt = idx / CC;
    int t = (int)(bt % TT);
    int token = tok[bt];
    const int half = CC/2;
    float pe;
    if (c < half) {
        float rate = powf(10000.f, -(float)c / half);
        pe = sinf((float)t * rate);
    } else {
        float rate = powf(10000.f, -(float)(c-half) / half);
        pe = cosf((float)t * rate);
    }
    out[idx] = emb[(long)token*CC + c] * 22.62741699796952f + pe;  // sqrt(512)
}

// ---------------------------------------------------------------------------
// Host-side launchers
// ---------------------------------------------------------------------------
static void setAttrs()
{
    cudaFuncSetAttribute((const void*)mma_gemm<128,128,16,64,32,false>,
        cudaFuncAttributeMaxDynamicSharedMemorySize, smemBytes<128,128,16>());
    cudaFuncSetAttribute((const void*)mma_gemm<128,64,16,32,32,false>,
        cudaFuncAttributeMaxDynamicSharedMemorySize, smemBytes<128,64,16>());
    cudaFuncSetAttribute((const void*)mma_gemm<128,128,16,64,32,true>,
        cudaFuncAttributeMaxDynamicSharedMemorySize, smemBytes<128,128,16>());
}

static void gemmP(const float* A, const float* B, float* C,
                  const float* bias, const float* resid,
                  int M, int N, int K, int relu)
{
    if (N >= 1024) {
        dim3 g(N/128, M/128, 1);
        mma_gemm<128,128,16,64,32,false><<<g,256,smemBytes<128,128,16>()>>>(
            A, A, B, C, bias, resid, K, K, N, N,
            1,1, 0,0,0, 0,0,0, 0,0,0, 0,0,0, 1.f, relu);
    } else {
        dim3 g(N/64, M/128, 1);
        mma_gemm<128,64,16,32,32,false><<<g,256,smemBytes<128,64,16>()>>>(
            A, A, B, C, bias, resid, K, K, N, N,
            1,1, 0,0,0, 0,0,0, 0,0,0, 0,0,0, 1.f, relu);
    }
}

// Full multi-head attention; att gets head-concat output [B*T, C].
static void attention(const float* xq, const float* xkv,
                      const float* wqkv, const float* bqkv,
                      float* qkv, float* s, float* att, int causal)
{
    // Fused QKV projection: z = j*16 + b*8 + h   (j selects A vs A2)
    {
        dim3 g(1, TT/128, 48);
        mma_gemm<128,64,16,32,32,false><<<g,256,smemBytes<128,64,16>()>>>(
            xq, xkv, wqkv, qkv, bqkv, nullptr,
            CC, CC, DD, DD,
            16, 8,
            0, (long)TT*CC, 0,                         // A: b stride
            (long)HH*CC*DD, 0, (long)CC*DD,            // B: j, h strides
            (long)QSZ, (long)HH*TT*DD, (long)TT*DD,    // C: j, b, h
            (long)HH*DD, 0, (long)DD,                  // bias: j, h
            1.f, 0);
    }
    // scores = Q @ K^T * sqrt(D)   (z = b*H+h)
    {
        dim3 g(TT/128, TT/128, BH);
        mma_gemm<128,128,16,64,32,true><<<g,256,smemBytes<128,128,16>()>>>(
            qkv, qkv, qkv + QSZ, s, nullptr, nullptr,
            DD, DD, DD, TT,
            1000000, 1,
            0, (long)TT*DD, 0,
            0, (long)TT*DD, 0,
            0, (long)TT*TT, 0,
            0,0,0,
            8.0f, 0);
    }
    softmax_k<<<BH*TT, 256>>>(s, causal);
    // out = P @ V, written at head-concat position (ldc = C, col offset h*D)
    {
        dim3 g(1, TT/128, BH);
        mma_gemm<128,64,16,32,32,false><<<g,256,smemBytes<128,64,16>()>>>(
            s, s, qkv + 2*QSZ, att, nullptr, nullptr,
            TT, TT, DD, CC,
            1000000, HH,
            0, (long)HH*TT*TT, (long)TT*TT,
            0, (long)HH*TT*DD, (long)TT*DD,
            0, (long)TT*CC, (long)DD,
            0,0,0,
            1.f, 0);
    }
}

extern "C" void kernel_launch(void* const* d_in, const int* in_sizes, int n_in,
                              void* d_out, int out_size)
{
    const int*   src     = (const int*)  d_in[0];
    const int*   tgt     = (const int*)  d_in[1];
    const float* src_emb = (const float*)d_in[2];
    const float* tgt_emb = (const float*)d_in[3];
    const float* e_wqkv  = (const float*)d_in[4];
    const float* e_bqkv  = (const float*)d_in[5];
    const float* e_wo    = (const float*)d_in[6];
    const float* e_bo    = (const float*)d_in[7];
    const float* e_ln1   = (const float*)d_in[8];
    const float* e_ln2   = (const float*)d_in[9];
    const float* e_fw1   = (const float*)d_in[10];
    const float* e_fb1   = (const float*)d_in[11];
    const float* e_fw2   = (const float*)d_in[12];
    const float* e_fb2   = (const float*)d_in[13];
    const float* dsw     = (const float*)d_in[14];
    const float* dsb     = (const float*)d_in[15];
    const float* dw1     = (const float*)d_in[16];
    const float* db1     = (const float*)d_in[17];
    const float* dln1    = (const float*)d_in[18];
    const float* dcw     = (const float*)d_in[19];
    const float* dcb     = (const float*)d_in[20];
    const float* dw2     = (const float*)d_in[21];
    const float* db2     = (const float*)d_in[22];
    const float* dln2    = (const float*)d_in[23];
    const float* dln3    = (const float*)d_in[24];
    const float* dfw1    = (const float*)d_in[25];
    const float* dfb1    = (const float*)d_in[26];
    const float* dfw2    = (const float*)d_in[27];
    const float* dfb2    = (const float*)d_in[28];
    const float* wf      = (const float*)d_in[29];
    const float* bf      = (const float*)d_in[30];
    float* out = (float*)d_out;

    setAttrs();

    float *gx,*gy,*gl,*gq,*gs,*ga,*gf;
    cudaGetSymbolAddress((void**)&gx, g_enc);
    cudaGetSymbolAddress((void**)&gy, g_dec);
    cudaGetSymbolAddress((void**)&gl, g_ln);
    cudaGetSymbolAddress((void**)&gq, g_qkv);
    cudaGetSymbolAddress((void**)&gs, g_s);
    cudaGetSymbolAddress((void**)&ga, g_att);
    cudaGetSymbolAddress((void**)&gf, g_ffn);

    const int embBlocks = (int)(((long)BB*TT*CC + 255) / 256);

    // ---------------- Encoder ----------------
    embed_k<<<embBlocks,256>>>(src, src_emb, gx);
    for (int l=0; l<LL; l++) {
        const float* ln1g = e_ln1 + (long)l*2*CC;
        ln_k<<<M2,256>>>(gx, gl, ln1g, ln1g + CC);
        attention(gl, gl,
                  e_wqkv + (long)l*3*HH*CC*DD, e_bqkv + (long)l*3*HH*DD,
                  gq, gs, ga, 0);
        gemmP(ga, e_wo + (long)l*CC*CC, gx, e_bo + (long)l*CC, gx, M2, CC, CC, 0);
        const float* ln2g = e_ln2 + (long)l*2*CC;
        ln_k<<<M2,256>>>(gx, gl, ln2g, ln2g + CC);
        gemmP(gl, e_fw1 + (long)l*CC*FF, gf, e_fb1 + (long)l*FF, nullptr, M2, FF, CC, 1);
        gemmP(gf, e_fw2 + (long)l*FF*CC, gx, e_fb2 + (long)l*CC, gx, M2, CC, FF, 0);
    }

    // ---------------- Decoder ----------------
    embed_k<<<embBlocks,256>>>(tgt, tgt_emb, gy);
    for (int l=0; l<LL; l++) {
        const float* l1 = dln1 + (long)l*2*CC;
        ln_k<<<M2,256>>>(gy, gl, l1, l1 + CC);
        attention(gl, gl,
                  dsw + (long)l*3*HH*CC*DD, dsb + (long)l*3*HH*DD,
                  gq, gs, ga, 1);                      // causal
        gemmP(ga, dw1 + (long)l*CC*CC, gy, db1 + (long)l*CC, gy, M2, CC, CC, 0);
        const float* l2 = dln2 + (long)l*2*CC;
        ln_k<<<M2,256>>>(gy, gl, l2, l2 + CC);
        attention(gl, gx,                              // cross: kv = enc_out
                  dcw + (long)l*3*HH*CC*DD, dcb + (long)l*3*HH*DD,
                  gq, gs, ga, 0);
        gemmP(ga, dw2 + (long)l*CC*CC, gy, db2 + (long)l*CC, gy, M2, CC, CC, 0);
        const float* l3 = dln3 + (long)l*2*CC;
        ln_k<<<M2,256>>>(gy, gl, l3, l3 + CC);
        gemmP(gl, dfw1 + (long)l*CC*FF, gf, dfb1 + (long)l*FF, nullptr, M2, FF, CC, 1);
        gemmP(gf, dfw2 + (long)l*FF*CC, gy, dfb2 + (long)l*CC, gy, M2, CC, FF, 0);
    }

    // ---------------- Final logits ----------------
    gemmP(gy, wf, out, bf, nullptr, M2, VV, CC, 0);
}

// round 5
// speedup vs baseline: 1.4982x; 1.0777x over previous
#include <cuda_runtime.h>
#include <cuda_bf16.h>
#include <math.h>
#include <stdint.h>

// Problem constants
#define LL 6
#define HH 8
#define CC 512
#define DD 64
#define FF 2048
#define VV 32000
#define BB 2
#define TT 1024
#define M2 (BB*TT)          // 2048 token rows
#define BH (BB*HH)          // 16 attention batches
#define QSZ (BH*TT*DD)      // one of Q/K/V

// ---------------------------------------------------------------------------
// Scratch (static device globals — allocation-free per harness rules)
// ---------------------------------------------------------------------------
__device__ float g_enc[M2*CC];
__device__ float g_dec[M2*CC];
__device__ float g_ln [M2*CC];
__device__ float g_qkv[3*QSZ];           // [j][b][h][T][D]
__device__ float g_s  [(long)BH*TT*TT];  // attention scores (64 MB)
__device__ float g_att[M2*CC];
__device__ float g_ffn[M2*FF];

// ---------------------------------------------------------------------------
// TF32 tensor-core helpers (3xTF32 fp32-emulation, pre-split at STS time)
// ---------------------------------------------------------------------------
__device__ __forceinline__ uint32_t f2tf(float f){
    uint32_t r; asm("cvt.rna.tf32.f32 %0, %1;" : "=r"(r) : "f"(f)); return r;
}
__device__ __forceinline__ uint2 split_tf(float v){
    uint32_t hi = f2tf(v);
    uint32_t lo = f2tf(v - __uint_as_float(hi));
    return make_uint2(hi, lo);
}
__device__ __forceinline__ void mma8(float* c, const uint32_t* a, const uint32_t* b){
    asm volatile("mma.sync.aligned.m16n8k8.row.col.f32.tf32.tf32.f32 "
        "{%0,%1,%2,%3},{%4,%5,%6,%7},{%8,%9},{%0,%1,%2,%3};"
        : "+f"(c[0]),"+f"(c[1]),"+f"(c[2]),"+f"(c[3])
        : "r"(a[0]),"r"(a[1]),"r"(a[2]),"r"(a[3]),"r"(b[0]),"r"(b[1]));
}

// ---------------------------------------------------------------------------
// Generic batched 3xTF32 GEMM (fp32-accurate), pre-split smem operands.
// Tile 128x64, 8 warps (warp tile 32x32), 2 CTAs/SM target.
// ---------------------------------------------------------------------------
template<int BM,int BN,int BK,int WM,int WN,bool TRANSB>
__global__ __launch_bounds__(256,2)
void mma_gemm(const float* __restrict__ A, const float* __restrict__ A2,
              const float* __restrict__ B, float* __restrict__ C,
              const float* __restrict__ bias, const float* __restrict__ resid,
              int K, int lda, int ldb, int ldc,
              int zDiv1, int zDiv2,
              long aS0, long aS1, long aS2,
              long bS0, long bS1, long bS2,
              long cS0, long cS1, long cS2,
              long sS0, long sS1, long sS2,
              float alpha, int relu)
{
    constexpr int BKP = BK + 4;     // uint2 row stride for A  (conflict-free reads)
    constexpr int BNP = BN + 4;     // uint2 row stride for B
    constexpr int WCOLS = BN / WN;
    constexpr int MITER = WM/16, NITER = WN/8;
    constexpr int AREG = BM*BK/(256*4);   // float4 per thread for A tile
    constexpr int BREG = BK*BN/(256*4);   // float4 per thread for B tile

    extern __shared__ uint2 sm2[];
    uint2* As = sm2;                    // [2][BM][BKP]
    uint2* Bs = sm2 + 2*BM*BKP;         // [2][BK][BNP]

    const int z = blockIdx.z;
    const int i0 = z / zDiv1, rem = z % zDiv1;
    const int i1 = rem / zDiv2, i2 = rem % zDiv2;
    const float* Ap = ((i0==0) ? A : A2) + i0*aS0 + i1*aS1 + i2*aS2;
    const float* Bp = B + i0*bS0 + i1*bS1 + i2*bS2;
    const long cOff = i0*cS0 + i1*cS1 + i2*cS2;
    float* Cp = C + cOff;
    const float* Rp = resid ? resid + cOff : nullptr;
    const float* bp = bias ? bias + i0*sS0 + i1*sS1 + i2*sS2 : nullptr;

    const int row0 = blockIdx.y * BM;
    const int col0 = blockIdx.x * BN;
    const int tid  = threadIdx.x;
    const int lane = tid & 31, w = tid >> 5;
    const int wr = w / WCOLS, wc = w % WCOLS;

    float acc[MITER][NITER][4];
    #pragma unroll
    for (int mi=0;mi<MITER;mi++)
        #pragma unroll
        for (int ni=0;ni<NITER;ni++)
            #pragma unroll
            for (int q=0;q<4;q++) acc[mi][ni][q] = 0.f;

    float4 ra[AREG], rb[BREG];

    auto ldgA = [&](int k0){
        #pragma unroll
        for (int i=0;i<AREG;i++){
            int id = tid + i*256;
            int r = id / (BK/4), c = (id % (BK/4))*4;
            ra[i] = *(const float4*)(Ap + (long)(row0+r)*lda + k0 + c);
        }
    };
    auto stsA = [&](int buf){
        #pragma unroll
        for (int i=0;i<AREG;i++){
            int id = tid + i*256;
            int r = id / (BK/4), c = (id % (BK/4))*4;
            uint2* d = As + buf*BM*BKP + r*BKP + c;
            uint2 s0 = split_tf(ra[i].x), s1 = split_tf(ra[i].y);
            uint2 s2 = split_tf(ra[i].z), s3 = split_tf(ra[i].w);
            ((uint4*)d)[0] = make_uint4(s0.x,s0.y,s1.x,s1.y);
            ((uint4*)d)[1] = make_uint4(s2.x,s2.y,s3.x,s3.y);
        }
    };
    auto ldgB = [&](int k0){
        #pragma unroll
        for (int i=0;i<BREG;i++){
            int id = tid + i*256;
            if (!TRANSB){
                int r = id / (BN/4), c = (id % (BN/4))*4;
                rb[i] = *(const float4*)(Bp + (long)(k0+r)*ldb + col0 + c);
            } else {
                int n = id / (BK/4), c = (id % (BK/4))*4;
                rb[i] = *(const float4*)(Bp + (long)(col0+n)*ldb + k0 + c);
            }
        }
    };
    auto stsB = [&](int buf){
        #pragma unroll
        for (int i=0;i<BREG;i++){
            int id = tid + i*256;
            if (!TRANSB){
                int r = id / (BN/4), c = (id % (BN/4))*4;
                uint2* d = Bs + buf*BK*BNP + r*BNP + c;
                uint2 s0 = split_tf(rb[i].x), s1 = split_tf(rb[i].y);
                uint2 s2 = split_tf(rb[i].z), s3 = split_tf(rb[i].w);
                ((uint4*)d)[0] = make_uint4(s0.x,s0.y,s1.x,s1.y);
                ((uint4*)d)[1] = make_uint4(s2.x,s2.y,s3.x,s3.y);
            } else {
                int n = id / (BK/4), c = (id % (BK/4))*4;
                uint2* base = Bs + buf*BK*BNP;
                base[(c+0)*BNP + n] = split_tf(rb[i].x);
                base[(c+1)*BNP + n] = split_tf(rb[i].y);
                base[(c+2)*BNP + n] = split_tf(rb[i].z);
                base[(c+3)*BNP + n] = split_tf(rb[i].w);
            }
        }
    };
    auto compute = [&](int buf){
        const uint2* Ab = As + buf*BM*BKP;
        const uint2* Bb = Bs + buf*BK*BNP;
        #pragma unroll
        for (int kk=0; kk<BK; kk+=8){
            const int kb = kk + (lane&3);
            uint2 aF[MITER][4]; uint2 bF[NITER][2];
            #pragma unroll
            for (int mi=0; mi<MITER; mi++){
                int m = wr*WM + mi*16 + (lane>>2);
                aF[mi][0] = Ab[(m  )*BKP + kb  ];
                aF[mi][1] = Ab[(m+8)*BKP + kb  ];
                aF[mi][2] = Ab[(m  )*BKP + kb+4];
                aF[mi][3] = Ab[(m+8)*BKP + kb+4];
            }
            #pragma unroll
            for (int ni=0; ni<NITER; ni++){
                int n = wc*WN + ni*8 + (lane>>2);
                bF[ni][0] = Bb[(kb  )*BNP + n];
                bF[ni][1] = Bb[(kb+4)*BNP + n];
            }
            #pragma unroll
            for (int mi=0; mi<MITER; mi++){
                uint32_t ah[4] = {aF[mi][0].x, aF[mi][1].x, aF[mi][2].x, aF[mi][3].x};
                uint32_t al[4] = {aF[mi][0].y, aF[mi][1].y, aF[mi][2].y, aF[mi][3].y};
                #pragma unroll
                for (int ni=0; ni<NITER; ni++){
                    uint32_t bh[2] = {bF[ni][0].x, bF[ni][1].x};
                    uint32_t bl[2] = {bF[ni][0].y, bF[ni][1].y};
                    mma8(acc[mi][ni], al, bh);
                    mma8(acc[mi][ni], ah, bl);
                    mma8(acc[mi][ni], ah, bh);
                }
            }
        }
    };

    const int nIter = K/BK;
    ldgA(0); ldgB(0);
    stsA(0); stsB(0);
    __syncthreads();
    for (int it=0; it<nIter; ++it){
        if (it+1 < nIter){ ldgA((it+1)*BK); ldgB((it+1)*BK); }
        compute(it & 1);
        if (it+1 < nIter){ stsA((it+1)&1); stsB((it+1)&1); }
        __syncthreads();
    }

    // Epilogue
    #pragma unroll
    for (int mi=0;mi<MITER;mi++){
        #pragma unroll
        for (int ni=0;ni<NITER;ni++){
            int r  = row0 + wr*WM + mi*16 + (lane>>2);
            int cl = col0 + wc*WN + ni*8 + 2*(lane&3);
            #pragma unroll
            for (int h=0; h<2; h++){
                int rr = r + 8*h;
                float x = acc[mi][ni][2*h  ]*alpha;
                float y = acc[mi][ni][2*h+1]*alpha;
                if (bp){ x += bp[cl]; y += bp[cl+1]; }
                if (Rp){ float2 t = *(const float2*)(Rp + (long)rr*ldc + cl);
                         x += t.x; y += t.y; }
                if (relu){ x = fmaxf(x,0.f); y = fmaxf(y,0.f); }
                *(float2*)(Cp + (long)rr*ldc + cl) = make_float2(x,y);
            }
        }
    }
}

// Shared-memory byte counts per instantiation
template<int BM,int BN,int BK>
constexpr int smemBytes(){ return (2*BM*(BK+4) + 2*BK*(BN+4)) * 8; }

// ---------------------------------------------------------------------------
// Block reductions (256 threads)
// ---------------------------------------------------------------------------
template<bool IS_MAX>
__device__ __forceinline__ float blockReduce(float v)
{
    __shared__ float sh[8];
    int lane = threadIdx.x & 31, w = threadIdx.x >> 5;
    #pragma unroll
    for (int o=16;o;o>>=1) {
        float u = __shfl_xor_sync(0xffffffffu, v, o);
        v = IS_MAX ? fmaxf(v,u) : v+u;
    }
    if (lane==0) sh[w] = v;
    __syncthreads();
    if (w==0) {
        v = (lane < 8) ? sh[lane] : (IS_MAX ? -__int_as_float(0x7f800000) : 0.f);
        #pragma unroll
        for (int o=4;o;o>>=1) {
            float u = __shfl_xor_sync(0xffffffffu, v, o);
            v = IS_MAX ? fmaxf(v,u) : v+u;
        }
        if (lane==0) sh[0] = v;
    }
    __syncthreads();
    float r = sh[0];
    __syncthreads();
    return r;
}

// ---------------------------------------------------------------------------
// Single-pass softmax: row of T=1024 lives in registers (float4/thread).
// Causal masks s>t (exp -> 0).
// ---------------------------------------------------------------------------
__global__ __launch_bounds__(256)
void softmax_k(float* __restrict__ s, int causal)
{
    long row = blockIdx.x;
    int t = (int)(row % TT);
    float4* p = (float4*)(s + row * (long)TT);
    int tid = threadIdx.x;
    int base = 4*tid;
    int n = causal ? (t+1) : TT;

    float4 v = p[tid];
    const float NEG = -__int_as_float(0x7f800000);
    if (base+0 >= n) v.x = NEG;
    if (base+1 >= n) v.y = NEG;
    if (base+2 >= n) v.z = NEG;
    if (base+3 >= n) v.w = NEG;

    float mx = fmaxf(fmaxf(v.x,v.y), fmaxf(v.z,v.w));
    mx = blockReduce<true>(mx);

    float4 e;
    e.x = __expf(v.x - mx); e.y = __expf(v.y - mx);
    e.z = __expf(v.z - mx); e.w = __expf(v.w - mx);
    float sum = (e.x + e.y) + (e.z + e.w);
    sum = blockReduce<false>(sum);
    float inv = 1.f / sum;
    e.x *= inv; e.y *= inv; e.z *= inv; e.w *= inv;
    p[tid] = e;
}

// ---------------------------------------------------------------------------
// LayerNorm: rows of C=512
// ---------------------------------------------------------------------------
__global__ __launch_bounds__(256)
void ln_k(const float* __restrict__ x, float* __restrict__ out,
          const float* __restrict__ gamma, const float* __restrict__ beta)
{
    long row = blockIdx.x;
    const float* xr = x + row*(long)CC;
    int tid = threadIdx.x;
    float v0 = xr[tid], v1 = xr[tid+256];
    float mu = blockReduce<false>(v0+v1) * (1.f/CC);
    float d0 = v0-mu, d1 = v1-mu;
    float var = blockReduce<false>(d0*d0 + d1*d1) * (1.f/CC);
    float inv = rsqrtf(var + 1e-5f);
    out[row*(long)CC + tid      ] = d0*inv*gamma[tid]     + beta[tid];
    out[row*(long)CC + tid + 256] = d1*inv*gamma[tid+256] + beta[tid+256];
}

// ---------------------------------------------------------------------------
// Embedding + positional encoding
// ---------------------------------------------------------------------------
__global__ __launch_bounds__(256)
void embed_k(const int* __restrict__ tok, const float* __restrict__ emb,
             float* __restrict__ out)
{
    long idx = (long)blockIdx.x*256 + threadIdx.x;
    if (idx >= (long)BB*TT*CC) return;
    int c = (int)(idx % CC);
    long bt = idx / CC;
    int t = (int)(bt % TT);
    int token = tok[bt];
    const int half = CC/2;
    float pe;
    if (c < half) {
        float rate = powf(10000.f, -(float)c / half);
        pe = sinf((float)t * rate);
    } else {
        float rate = powf(10000.f, -(float)(c-half) / half);
        pe = cosf((float)t * rate);
    }
    out[idx] = emb[(long)token*CC + c] * 22.62741699796952f + pe;  // sqrt(512)
}

// ---------------------------------------------------------------------------
// Host-side launchers
// ---------------------------------------------------------------------------
static void setAttrs()
{
    cudaFuncSetAttribute((const void*)mma_gemm<128,64,16,32,32,false>,
        cudaFuncAttributeMaxDynamicSharedMemorySize, smemBytes<128,64,16>());
    cudaFuncSetAttribute((const void*)mma_gemm<128,64,16,32,32,true>,
        cudaFuncAttributeMaxDynamicSharedMemorySize, smemBytes<128,64,16>());
}

static void gemmP(const float* A, const float* B, float* C,
                  const float* bias, const float* resid,
                  int M, int N, int K, int relu)
{
    dim3 g(N/64, M/128, 1);
    mma_gemm<128,64,16,32,32,false><<<g,256,smemBytes<128,64,16>()>>>(
        A, A, B, C, bias, resid, K, K, N, N,
        1,1, 0,0,0, 0,0,0, 0,0,0, 0,0,0, 1.f, relu);
}

// Full multi-head attention; att gets head-concat output [B*T, C].
static void attention(const float* xq, const float* xkv,
                      const float* wqkv, const float* bqkv,
                      float* qkv, float* s, float* att, int causal)
{
    // Fused QKV projection: z = j*16 + b*8 + h   (j selects A vs A2)
    {
        dim3 g(1, TT/128, 48);
        mma_gemm<128,64,16,32,32,false><<<g,256,smemBytes<128,64,16>()>>>(
            xq, xkv, wqkv, qkv, bqkv, nullptr,
            CC, CC, DD, DD,
            16, 8,
            0, (long)TT*CC, 0,                         // A: b stride
            (long)HH*CC*DD, 0, (long)CC*DD,            // B: j, h strides
            (long)QSZ, (long)HH*TT*DD, (long)TT*DD,    // C: j, b, h
            (long)HH*DD, 0, (long)DD,                  // bias: j, h
            1.f, 0);
    }
    // scores = Q @ K^T * sqrt(D)   (z = b*H+h)
    {
        dim3 g(TT/64, TT/128, BH);
        mma_gemm<128,64,16,32,32,true><<<g,256,smemBytes<128,64,16>()>>>(
            qkv, qkv, qkv + QSZ, s, nullptr, nullptr,
            DD, DD, DD, TT,
            1000000, 1,
            0, (long)TT*DD, 0,
            0, (long)TT*DD, 0,
            0, (long)TT*TT, 0,
            0,0,0,
            8.0f, 0);
    }
    softmax_k<<<BH*TT, 256>>>(s, causal);
    // out = P @ V, written at head-concat position (ldc = C, col offset h*D)
    {
        dim3 g(1, TT/128, BH);
        mma_gemm<128,64,16,32,32,false><<<g,256,smemBytes<128,64,16>()>>>(
            s, s, qkv + 2*QSZ, att, nullptr, nullptr,
            TT, TT, DD, CC,
            1000000, HH,
            0, (long)HH*TT*TT, (long)TT*TT,
            0, (long)HH*TT*DD, (long)TT*DD,
            0, (long)TT*CC, (long)DD,
            0,0,0,
            1.f, 0);
    }
}

extern "C" void kernel_launch(void* const* d_in, const int* in_sizes, int n_in,
                              void* d_out, int out_size)
{
    const int*   src     = (const int*)  d_in[0];
    const int*   tgt     = (const int*)  d_in[1];
    const float* src_emb = (const float*)d_in[2];
    const float* tgt_emb = (const float*)d_in[3];
    const float* e_wqkv  = (const float*)d_in[4];
    const float* e_bqkv  = (const float*)d_in[5];
    const float* e_wo    = (const float*)d_in[6];
    const float* e_bo    = (const float*)d_in[7];
    const float* e_ln1   = (const float*)d_in[8];
    const float* e_ln2   = (const float*)d_in[9];
    const float* e_fw1   = (const float*)d_in[10];
    const float* e_fb1   = (const float*)d_in[11];
    const float* e_fw2   = (const float*)d_in[12];
    const float* e_fb2   = (const float*)d_in[13];
    const float* dsw     = (const float*)d_in[14];
    const float* dsb     = (const float*)d_in[15];
    const float* dw1     = (const float*)d_in[16];
    const float* db1     = (const float*)d_in[17];
    const float* dln1    = (const float*)d_in[18];
    const float* dcw     = (const float*)d_in[19];
    const float* dcb     = (const float*)d_in[20];
    const float* dw2     = (const float*)d_in[21];
    const float* db2     = (const float*)d_in[22];
    const float* dln2    = (const float*)d_in[23];
    const float* dln3    = (const float*)d_in[24];
    const float* dfw1    = (const float*)d_in[25];
    const float* dfb1    = (const float*)d_in[26];
    const float* dfw2    = (const float*)d_in[27];
    const float* dfb2    = (const float*)d_in[28];
    const float* wf      = (const float*)d_in[29];
    const float* bf      = (const float*)d_in[30];
    float* out = (float*)d_out;

    setAttrs();

    float *gx,*gy,*gl,*gq,*gs,*ga,*gf;
    cudaGetSymbolAddress((void**)&gx, g_enc);
    cudaGetSymbolAddress((void**)&gy, g_dec);
    cudaGetSymbolAddress((void**)&gl, g_ln);
    cudaGetSymbolAddress((void**)&gq, g_qkv);
    cudaGetSymbolAddress((void**)&gs, g_s);
    cudaGetSymbolAddress((void**)&ga, g_att);
    cudaGetSymbolAddress((void**)&gf, g_ffn);

    const int embBlocks = (int)(((long)BB*TT*CC + 255) / 256);

    // ---------------- Encoder ----------------
    embed_k<<<embBlocks,256>>>(src, src_emb, gx);
    for (int l=0; l<LL; l++) {
        const float* ln1g = e_ln1 + (long)l*2*CC;
        ln_k<<<M2,256>>>(gx, gl, ln1g, ln1g + CC);
        attention(gl, gl,
                  e_wqkv + (long)l*3*HH*CC*DD, e_bqkv + (long)l*3*HH*DD,
                  gq, gs, ga, 0);
        gemmP(ga, e_wo + (long)l*CC*CC, gx, e_bo + (long)l*CC, gx, M2, CC, CC, 0);
        const float* ln2g = e_ln2 + (long)l*2*CC;
        ln_k<<<M2,256>>>(gx, gl, ln2g, ln2g + CC);
        gemmP(gl, e_fw1 + (long)l*CC*FF, gf, e_fb1 + (long)l*FF, nullptr, M2, FF, CC, 1);
        gemmP(gf, e_fw2 + (long)l*FF*CC, gx, e_fb2 + (long)l*CC, gx, M2, CC, FF, 0);
    }

    // ---------------- Decoder ----------------
    embed_k<<<embBlocks,256>>>(tgt, tgt_emb, gy);
    for (int l=0; l<LL; l++) {
        const float* l1 = dln1 + (long)l*2*CC;
        ln_k<<<M2,256>>>(gy, gl, l1, l1 + CC);
        attention(gl, gl,
                  dsw + (long)l*3*HH*CC*DD, dsb + (long)l*3*HH*DD,
                  gq, gs, ga, 1);                      // causal
        gemmP(ga, dw1 + (long)l*CC*CC, gy, db1 + (long)l*CC, gy, M2, CC, CC, 0);
        const float* l2 = dln2 + (long)l*2*CC;
        ln_k<<<M2,256>>>(gy, gl, l2, l2 + CC);
        attention(gl, gx,                              // cross: kv = enc_out
                  dcw + (long)l*3*HH*CC*DD, dcb + (long)l*3*HH*DD,
                  gq, gs, ga, 0);
        gemmP(ga, dw2 + (long)l*CC*CC, gy, db2 + (long)l*CC, gy, M2, CC, CC, 0);
        const float* l3 = dln3 + (long)l*2*CC;
        ln_k<<<M2,256>>>(gy, gl, l3, l3 + CC);
        gemmP(gl, dfw1 + (long)l*CC*FF, gf, dfb1 + (long)l*FF, nullptr, M2, FF, CC, 1);
        gemmP(gf, dfw2 + (long)l*FF*CC, gy, dfb2 + (long)l*CC, gy, M2, CC, FF, 0);
    }

    // ---------------- Final logits ----------------
    gemmP(gy, wf, out, bf, nullptr, M2, VV, CC, 0);
}

// round 6
// speedup vs baseline: 2.8359x; 1.8929x over previous
#include <cuda_runtime.h>
#include <cuda_bf16.h>
#include <math.h>
#include <stdint.h>

// Problem constants
#define LL 6
#define HH 8
#define CC 512
#define DD 64
#define FF 2048
#define VV 32000
#define BB 2
#define TT 1024
#define M2 (BB*TT)          // 2048 token rows
#define BH (BB*HH)          // 16 attention batches
#define QSZ (BH*TT*DD)      // one of Q/K/V

// ---------------------------------------------------------------------------
// Scratch (static device globals — allocation-free per harness rules)
// ---------------------------------------------------------------------------
__device__ float g_enc[M2*CC];
__device__ float g_dec[M2*CC];
__device__ float g_ln [M2*CC];
__device__ float g_qkv[3*QSZ];           // [j][b][h][T][D]
__device__ float g_s  [(long)BH*TT*TT];  // attention scores (64 MB)
__device__ float g_att[M2*CC];
__device__ float g_ffn[M2*FF];

// ---------------------------------------------------------------------------
// bf16x2 double-bf16 helpers: v = hi + lo, hi/lo bf16. 3 MMAs ~ fp32-ish.
// ---------------------------------------------------------------------------
__device__ __forceinline__ uint32_t pk(float k0, float k1){
    // pack: low half = bf16(k0), high half = bf16(k1)
    uint32_t r; asm("cvt.rn.bf16x2.f32 %0, %1, %2;" : "=r"(r) : "f"(k1), "f"(k0));
    return r;
}
__device__ __forceinline__ uint2 split2(float x0, float x1){
    uint32_t h = pk(x0, x1);
    float h0 = __uint_as_float(h << 16);
    float h1 = __uint_as_float(h & 0xffff0000u);
    uint32_t l = pk(x0 - h0, x1 - h1);
    return make_uint2(h, l);
}
__device__ __forceinline__ void mma16(float* c, const uint32_t* a, const uint32_t* b){
    asm volatile("mma.sync.aligned.m16n8k16.row.col.f32.bf16.bf16.f32 "
        "{%0,%1,%2,%3},{%4,%5,%6,%7},{%8,%9},{%0,%1,%2,%3};"
        : "+f"(c[0]),"+f"(c[1]),"+f"(c[2]),"+f"(c[3])
        : "r"(a[0]),"r"(a[1]),"r"(a[2]),"r"(a[3]),"r"(b[0]),"r"(b[1]));
}

// ---------------------------------------------------------------------------
// Generic batched bf16x2 GEMM (near-fp32), pre-split smem operands.
// Tile 128x64, BK=32, 8 warps (warp tile 32x32), 2 CTAs/SM.
//  z decomposed: i0 = z/zDiv1; rem = z%zDiv1; i1 = rem/zDiv2; i2 = rem%zDiv2
//  A pointer = (i0==0 ? A : A2) + strides  (QKV fusion trick)
//  B row-major [K,N] (or [N,K] when TRANSB).
//  C = alpha*A@B (+bias) (+resid) (relu?)
// ---------------------------------------------------------------------------
template<int BM,int BN,int BK,int WM,int WN,bool TRANSB>
__global__ __launch_bounds__(256,2)
void mma_gemm(const float* __restrict__ A, const float* __restrict__ A2,
              const float* __restrict__ B, float* __restrict__ C,
              const float* __restrict__ bias, const float* __restrict__ resid,
              int K, int lda, int ldb, int ldc,
              int zDiv1, int zDiv2,
              long aS0, long aS1, long aS2,
              long bS0, long bS1, long bS2,
              long cS0, long cS1, long cS2,
              long sS0, long sS1, long sS2,
              float alpha, int relu)
{
    constexpr int KP  = BK/2;       // k-pairs per tile
    constexpr int BKP2 = KP + 4;    // A row stride in uint2 (20 -> 40 words, conflict-free)
    constexpr int BNP2 = BN + 4;    // B row stride in uint2 (68 -> 136 ≡ 8 mod 32)
    constexpr int WCOLS = BN / WN;
    constexpr int MITER = WM/16, NITER = WN/8;
    constexpr int AREG = BM*BK/(256*4);   // float4 per thread for A tile (4)

    extern __shared__ uint2 sm2[];
    uint2* As = sm2;                    // [2][BM][BKP2]
    uint2* Bs = sm2 + 2*BM*BKP2;        // [2][KP][BNP2]

    const int z = blockIdx.z;
    const int i0 = z / zDiv1, rem = z % zDiv1;
    const int i1 = rem / zDiv2, i2 = rem % zDiv2;
    const float* Ap = ((i0==0) ? A : A2) + i0*aS0 + i1*aS1 + i2*aS2;
    const float* Bp = B + i0*bS0 + i1*bS1 + i2*bS2;
    const long cOff = i0*cS0 + i1*cS1 + i2*cS2;
    float* Cp = C + cOff;
    const float* Rp = resid ? resid + cOff : nullptr;
    const float* bp = bias ? bias + i0*sS0 + i1*sS1 + i2*sS2 : nullptr;

    const int row0 = blockIdx.y * BM;
    const int col0 = blockIdx.x * BN;
    const int tid  = threadIdx.x;
    const int lane = tid & 31, w = tid >> 5;
    const int wr = w / WCOLS, wc = w % WCOLS;
    const int g  = lane >> 2, cq = lane & 3;

    float acc[MITER][NITER][4];
    #pragma unroll
    for (int mi=0;mi<MITER;mi++)
        #pragma unroll
        for (int ni=0;ni<NITER;ni++)
            #pragma unroll
            for (int q=0;q<4;q++) acc[mi][ni][q] = 0.f;

    float4 ra[AREG], rb[2];

    auto ldgA = [&](int k0){
        #pragma unroll
        for (int i=0;i<AREG;i++){
            int id = tid + i*256;
            int r = id / (BK/4), c4 = id % (BK/4);
            ra[i] = *(const float4*)(Ap + (long)(row0+r)*lda + k0 + c4*4);
        }
    };
    auto stsA = [&](int buf){
        #pragma unroll
        for (int i=0;i<AREG;i++){
            int id = tid + i*256;
            int r = id / (BK/4), c4 = id % (BK/4);
            uint2* d = As + buf*BM*BKP2 + r*BKP2 + c4*2;
            d[0] = split2(ra[i].x, ra[i].y);
            d[1] = split2(ra[i].z, ra[i].w);
        }
    };
    auto ldgB = [&](int k0){
        if (!TRANSB){
            // thread -> (k-pair, 4n): 2 rows of float4
            int kp = tid / (BN/4), n4 = tid % (BN/4);
            if (kp < KP){
                const float* src = Bp + (long)(k0 + 2*kp)*ldb + col0 + n4*4;
                rb[0] = *(const float4*)(src);
                rb[1] = *(const float4*)(src + ldb);
            }
        } else {
            #pragma unroll
            for (int j=0;j<2;j++){
                int id = tid + j*256;
                int n = id / (BK/4), kg = id % (BK/4);
                rb[j] = *(const float4*)(Bp + (long)(col0+n)*ldb + k0 + kg*4);
            }
        }
    };
    auto stsB = [&](int buf){
        uint2* base = Bs + buf*KP*BNP2;
        if (!TRANSB){
            int kp = tid / (BN/4), n4 = tid % (BN/4);
            if (kp < KP){
                uint2* d = base + kp*BNP2 + n4*4;
                d[0] = split2(rb[0].x, rb[1].x);
                d[1] = split2(rb[0].y, rb[1].y);
                d[2] = split2(rb[0].z, rb[1].z);
                d[3] = split2(rb[0].w, rb[1].w);
            }
        } else {
            #pragma unroll
            for (int j=0;j<2;j++){
                int id = tid + j*256;
                int n = id / (BK/4), kg = id % (BK/4);
                base[(kg*2  )*BNP2 + n] = split2(rb[j].x, rb[j].y);
                base[(kg*2+1)*BNP2 + n] = split2(rb[j].z, rb[j].w);
            }
        }
    };
    auto compute = [&](int buf){
        const uint2* Ab = As + buf*BM*BKP2;
        const uint2* Bb = Bs + buf*KP*BNP2;
        #pragma unroll
        for (int s=0; s<BK/16; s++){
            const int pb = s*8 + cq;
            uint2 aF[MITER][4]; uint2 bF[NITER][2];
            #pragma unroll
            for (int mi=0; mi<MITER; mi++){
                int m = wr*WM + mi*16 + g;
                aF[mi][0] = Ab[(m  )*BKP2 + pb  ];
                aF[mi][1] = Ab[(m+8)*BKP2 + pb  ];
                aF[mi][2] = Ab[(m  )*BKP2 + pb+4];
                aF[mi][3] = Ab[(m+8)*BKP2 + pb+4];
            }
            #pragma unroll
            for (int ni=0; ni<NITER; ni++){
                int n = wc*WN + ni*8 + g;
                bF[ni][0] = Bb[(pb  )*BNP2 + n];
                bF[ni][1] = Bb[(pb+4)*BNP2 + n];
            }
            #pragma unroll
            for (int mi=0; mi<MITER; mi++){
                uint32_t ah[4] = {aF[mi][0].x, aF[mi][1].x, aF[mi][2].x, aF[mi][3].x};
                uint32_t al[4] = {aF[mi][0].y, aF[mi][1].y, aF[mi][2].y, aF[mi][3].y};
                #pragma unroll
                for (int ni=0; ni<NITER; ni++){
                    uint32_t bh[2] = {bF[ni][0].x, bF[ni][1].x};
                    uint32_t bl[2] = {bF[ni][0].y, bF[ni][1].y};
                    mma16(acc[mi][ni], al, bh);
                    mma16(acc[mi][ni], ah, bl);
                    mma16(acc[mi][ni], ah, bh);
                }
            }
        }
    };

    const int nIter = K/BK;
    ldgA(0); ldgB(0);
    stsA(0); stsB(0);
    __syncthreads();
    for (int it=0; it<nIter; ++it){
        if (it+1 < nIter){ ldgA((it+1)*BK); ldgB((it+1)*BK); }
        compute(it & 1);
        if (it+1 < nIter){ stsA((it+1)&1); stsB((it+1)&1); }
        __syncthreads();
    }

    // Epilogue
    #pragma unroll
    for (int mi=0;mi<MITER;mi++){
        #pragma unroll
        for (int ni=0;ni<NITER;ni++){
            int r  = row0 + wr*WM + mi*16 + g;
            int cl = col0 + wc*WN + ni*8 + 2*cq;
            #pragma unroll
            for (int h=0; h<2; h++){
                int rr = r + 8*h;
                float x = acc[mi][ni][2*h  ]*alpha;
                float y = acc[mi][ni][2*h+1]*alpha;
                if (bp){ x += bp[cl]; y += bp[cl+1]; }
                if (Rp){ float2 t = *(const float2*)(Rp + (long)rr*ldc + cl);
                         x += t.x; y += t.y; }
                if (relu){ x = fmaxf(x,0.f); y = fmaxf(y,0.f); }
                *(float2*)(Cp + (long)rr*ldc + cl) = make_float2(x,y);
            }
        }
    }
}

// Shared-memory byte counts per instantiation
template<int BM,int BN,int BK>
constexpr int smemBytes(){ return (2*BM*(BK/2+4) + 2*(BK/2)*(BN+4)) * 8; }

// ---------------------------------------------------------------------------
// Block reductions (256 threads)
// ---------------------------------------------------------------------------
template<bool IS_MAX>
__device__ __forceinline__ float blockReduce(float v)
{
    __shared__ float sh[8];
    int lane = threadIdx.x & 31, w = threadIdx.x >> 5;
    #pragma unroll
    for (int o=16;o;o>>=1) {
        float u = __shfl_xor_sync(0xffffffffu, v, o);
        v = IS_MAX ? fmaxf(v,u) : v+u;
    }
    if (lane==0) sh[w] = v;
    __syncthreads();
    if (w==0) {
        v = (lane < 8) ? sh[lane] : (IS_MAX ? -__int_as_float(0x7f800000) : 0.f);
        #pragma unroll
        for (int o=4;o;o>>=1) {
            float u = __shfl_xor_sync(0xffffffffu, v, o);
            v = IS_MAX ? fmaxf(v,u) : v+u;
        }
        if (lane==0) sh[0] = v;
    }
    __syncthreads();
    float r = sh[0];
    __syncthreads();
    return r;
}

// ---------------------------------------------------------------------------
// Single-pass softmax: row of T=1024 in registers (float4/thread).
// ---------------------------------------------------------------------------
__global__ __launch_bounds__(256)
void softmax_k(float* __restrict__ s, int causal)
{
    long row = blockIdx.x;
    int t = (int)(row % TT);
    float4* p = (float4*)(s + row * (long)TT);
    int tid = threadIdx.x;
    int base = 4*tid;
    int n = causal ? (t+1) : TT;

    float4 v = p[tid];
    const float NEG = -__int_as_float(0x7f800000);
    if (base+0 >= n) v.x = NEG;
    if (base+1 >= n) v.y = NEG;
    if (base+2 >= n) v.z = NEG;
    if (base+3 >= n) v.w = NEG;

    float mx = fmaxf(fmaxf(v.x,v.y), fmaxf(v.z,v.w));
    mx = blockReduce<true>(mx);

    float4 e;
    e.x = __expf(v.x - mx); e.y = __expf(v.y - mx);
    e.z = __expf(v.z - mx); e.w = __expf(v.w - mx);
    float sum = (e.x + e.y) + (e.z + e.w);
    sum = blockReduce<false>(sum);
    float inv = 1.f / sum;
    e.x *= inv; e.y *= inv; e.z *= inv; e.w *= inv;
    p[tid] = e;
}

// ---------------------------------------------------------------------------
// LayerNorm: rows of C=512
// ---------------------------------------------------------------------------
__global__ __launch_bounds__(256)
void ln_k(const float* __restrict__ x, float* __restrict__ out,
          const float* __restrict__ gamma, const float* __restrict__ beta)
{
    long row = blockIdx.x;
    const float* xr = x + row*(long)CC;
    int tid = threadIdx.x;
    float v0 = xr[tid], v1 = xr[tid+256];
    float mu = blockReduce<false>(v0+v1) * (1.f/CC);
    float d0 = v0-mu, d1 = v1-mu;
    float var = blockReduce<false>(d0*d0 + d1*d1) * (1.f/CC);
    float inv = rsqrtf(var + 1e-5f);
    out[row*(long)CC + tid      ] = d0*inv*gamma[tid]     + beta[tid];
    out[row*(long)CC + tid + 256] = d1*inv*gamma[tid+256] + beta[tid+256];
}

// ---------------------------------------------------------------------------
// Embedding + positional encoding
// ---------------------------------------------------------------------------
__global__ __launch_bounds__(256)
void embed_k(const int* __restrict__ tok, const float* __restrict__ emb,
             float* __restrict__ out)
{
    long idx = (long)blockIdx.x*256 + threadIdx.x;
    if (idx >= (long)BB*TT*CC) return;
    int c = (int)(idx % CC);
    long bt = idx / CC;
    int t = (int)(bt % TT);
    int token = tok[bt];
    const int half = CC/2;
    float pe;
    if (c < half) {
        float rate = powf(10000.f, -(float)c / half);
        pe = sinf((float)t * rate);
    } else {
        float rate = powf(10000.f, -(float)(c-half) / half);
        pe = cosf((float)t * rate);
    }
    out[idx] = emb[(long)token*CC + c] * 22.62741699796952f + pe;  // sqrt(512)
}

// ---------------------------------------------------------------------------
// Host-side launchers
// ---------------------------------------------------------------------------
static void setAttrs()
{
    cudaFuncSetAttribute((const void*)mma_gemm<128,64,32,32,32,false>,
        cudaFuncAttributeMaxDynamicSharedMemorySize, smemBytes<128,64,32>());
    cudaFuncSetAttribute((const void*)mma_gemm<128,64,32,32,32,true>,
        cudaFuncAttributeMaxDynamicSharedMemorySize, smemBytes<128,64,32>());
}

static void gemmP(const float* A, const float* B, float* C,
                  const float* bias, const float* resid,
                  int M, int N, int K, int relu)
{
    dim3 g(N/64, M/128, 1);
    mma_gemm<128,64,32,32,32,false><<<g,256,smemBytes<128,64,32>()>>>(
        A, A, B, C, bias, resid, K, K, N, N,
        1,1, 0,0,0, 0,0,0, 0,0,0, 0,0,0, 1.f, relu);
}

// Full multi-head attention; att gets head-concat output [B*T, C].
static void attention(const float* xq, const float* xkv,
                      const float* wqkv, const float* bqkv,
                      float* qkv, float* s, float* att, int causal)
{
    // Fused QKV projection: z = j*16 + b*8 + h   (j selects A vs A2)
    {
        dim3 g(1, TT/128, 48);
        mma_gemm<128,64,32,32,32,false><<<g,256,smemBytes<128,64,32>()>>>(
            xq, xkv, wqkv, qkv, bqkv, nullptr,
            CC, CC, DD, DD,
            16, 8,
            0, (long)TT*CC, 0,                         // A: b stride
            (long)HH*CC*DD, 0, (long)CC*DD,            // B: j, h strides
            (long)QSZ, (long)HH*TT*DD, (long)TT*DD,    // C: j, b, h
            (long)HH*DD, 0, (long)DD,                  // bias: j, h
            1.f, 0);
    }
    // scores = Q @ K^T * sqrt(D)   (z = b*H+h)
    {
        dim3 g(TT/64, TT/128, BH);
        mma_gemm<128,64,32,32,32,true><<<g,256,smemBytes<128,64,32>()>>>(
            qkv, qkv, qkv + QSZ, s, nullptr, nullptr,
            DD, DD, DD, TT,
            1000000, 1,
            0, (long)TT*DD, 0,
            0, (long)TT*DD, 0,
            0, (long)TT*TT, 0,
            0,0,0,
            8.0f, 0);
    }
    softmax_k<<<BH*TT, 256>>>(s, causal);
    // out = P @ V, written at head-concat position (ldc = C, col offset h*D)
    {
        dim3 g(1, TT/128, BH);
        mma_gemm<128,64,32,32,32,false><<<g,256,smemBytes<128,64,32>()>>>(
            s, s, qkv + 2*QSZ, att, nullptr, nullptr,
            TT, TT, DD, CC,
            1000000, HH,
            0, (long)HH*TT*TT, (long)TT*TT,
            0, (long)HH*TT*DD, (long)TT*DD,
            0, (long)TT*CC, (long)DD,
            0,0,0,
            1.f, 0);
    }
}

extern "C" void kernel_launch(void* const* d_in, const int* in_sizes, int n_in,
                              void* d_out, int out_size)
{
    const int*   src     = (const int*)  d_in[0];
    const int*   tgt     = (const int*)  d_in[1];
    const float* src_emb = (const float*)d_in[2];
    const float* tgt_emb = (const float*)d_in[3];
    const float* e_wqkv  = (const float*)d_in[4];
    const float* e_bqkv  = (const float*)d_in[5];
    const float* e_wo    = (const float*)d_in[6];
    const float* e_bo    = (const float*)d_in[7];
    const float* e_ln1   = (const float*)d_in[8];
    const float* e_ln2   = (const float*)d_in[9];
    const float* e_fw1   = (const float*)d_in[10];
    const float* e_fb1   = (const float*)d_in[11];
    const float* e_fw2   = (const float*)d_in[12];
    const float* e_fb2   = (const float*)d_in[13];
    const float* dsw     = (const float*)d_in[14];
    const float* dsb     = (const float*)d_in[15];
    const float* dw1     = (const float*)d_in[16];
    const float* db1     = (const float*)d_in[17];
    const float* dln1    = (const float*)d_in[18];
    const float* dcw     = (const float*)d_in[19];
    const float* dcb     = (const float*)d_in[20];
    const float* dw2     = (const float*)d_in[21];
    const float* db2     = (const float*)d_in[22];
    const float* dln2    = (const float*)d_in[23];
    const float* dln3    = (const float*)d_in[24];
    const float* dfw1    = (const float*)d_in[25];
    const float* dfb1    = (const float*)d_in[26];
    const float* dfw2    = (const float*)d_in[27];
    const float* dfb2    = (const float*)d_in[28];
    const float* wf      = (const float*)d_in[29];
    const float* bf      = (const float*)d_in[30];
    float* out = (float*)d_out;

    setAttrs();

    float *gx,*gy,*gl,*gq,*gs,*ga,*gf;
    cudaGetSymbolAddress((void**)&gx, g_enc);
    cudaGetSymbolAddress((void**)&gy, g_dec);
    cudaGetSymbolAddress((void**)&gl, g_ln);
    cudaGetSymbolAddress((void**)&gq, g_qkv);
    cudaGetSymbolAddress((void**)&gs, g_s);
    cudaGetSymbolAddress((void**)&ga, g_att);
    cudaGetSymbolAddress((void**)&gf, g_ffn);

    const int embBlocks = (int)(((long)BB*TT*CC + 255) / 256);

    // ---------------- Encoder ----------------
    embed_k<<<embBlocks,256>>>(src, src_emb, gx);
    for (int l=0; l<LL; l++) {
        const float* ln1g = e_ln1 + (long)l*2*CC;
        ln_k<<<M2,256>>>(gx, gl, ln1g, ln1g + CC);
        attention(gl, gl,
                  e_wqkv + (long)l*3*HH*CC*DD, e_bqkv + (long)l*3*HH*DD,
                  gq, gs, ga, 0);
        gemmP(ga, e_wo + (long)l*CC*CC, gx, e_bo + (long)l*CC, gx, M2, CC, CC, 0);
        const float* ln2g = e_ln2 + (long)l*2*CC;
        ln_k<<<M2,256>>>(gx, gl, ln2g, ln2g + CC);
        gemmP(gl, e_fw1 + (long)l*CC*FF, gf, e_fb1 + (long)l*FF, nullptr, M2, FF, CC, 1);
        gemmP(gf, e_fw2 + (long)l*FF*CC, gx, e_fb2 + (long)l*CC, gx, M2, CC, FF, 0);
    }

    // ---------------- Decoder ----------------
    embed_k<<<embBlocks,256>>>(tgt, tgt_emb, gy);
    for (int l=0; l<LL; l++) {
        const float* l1 = dln1 + (long)l*2*CC;
        ln_k<<<M2,256>>>(gy, gl, l1, l1 + CC);
        attention(gl, gl,
                  dsw + (long)l*3*HH*CC*DD, dsb + (long)l*3*HH*DD,
                  gq, gs, ga, 1);                      // causal
        gemmP(ga, dw1 + (long)l*CC*CC, gy, db1 + (long)l*CC, gy, M2, CC, CC, 0);
        const float* l2 = dln2 + (long)l*2*CC;
        ln_k<<<M2,256>>>(gy, gl, l2, l2 + CC);
        attention(gl, gx,                              // cross: kv = enc_out
                  dcw + (long)l*3*HH*CC*DD, dcb + (long)l*3*HH*DD,
                  gq, gs, ga, 0);
        gemmP(ga, dw2 + (long)l*CC*CC, gy, db2 + (long)l*CC, gy, M2, CC, CC, 0);
        const float* l3 = dln3 + (long)l*2*CC;
        ln_k<<<M2,256>>>(gy, gl, l3, l3 + CC);
        gemmP(gl, dfw1 + (long)l*CC*FF, gf, dfb1 + (long)l*FF, nullptr, M2, FF, CC, 1);
        gemmP(gf, dfw2 + (long)l*FF*CC, gy, dfb2 + (long)l*CC, gy, M2, CC, FF, 0);
    }

    // ---------------- Final logits ----------------
    gemmP(gy, wf, out, bf, nullptr, M2, VV, CC, 0);
}

// round 7
// speedup vs baseline: 3.1699x; 1.1178x over previous
#include <cuda_runtime.h>
#include <cuda_bf16.h>
#include <math.h>
#include <stdint.h>

// Problem constants
#define LL 6
#define HH 8
#define CC 512
#define DD 64
#define FF 2048
#define VV 32000
#define BB 2
#define TT 1024
#define M2 (BB*TT)          // 2048 token rows
#define BH (BB*HH)          // 16 attention batches
#define QSZ (BH*TT*DD)      // one of Q/K/V

// ---------------------------------------------------------------------------
// Scratch (static device globals — allocation-free per harness rules)
// ---------------------------------------------------------------------------
__device__ float g_enc[M2*CC];
__device__ float g_dec[M2*CC];
__device__ float g_ln [M2*CC];
__device__ float g_qkv[3*QSZ];           // [j][b][h][T][D]
__device__ float g_s  [(long)BH*TT*TT];  // attention scores (64 MB)
__device__ float g_att[M2*CC];
__device__ float g_ffn[M2*FF];

// ---------------------------------------------------------------------------
// bf16x2 double-bf16 helpers: v = hi + lo. 3 bf16 MMAs ~ fp32-ish.
// ---------------------------------------------------------------------------
__device__ __forceinline__ uint32_t pk(float k0, float k1){
    // pack: low half = bf16(k0), high half = bf16(k1)
    uint32_t r; asm("cvt.rn.bf16x2.f32 %0, %1, %2;" : "=r"(r) : "f"(k1), "f"(k0));
    return r;
}
__device__ __forceinline__ void split4(const float4& v, uint2& hi, uint2& lo){
    uint32_t h0 = pk(v.x, v.y), h1 = pk(v.z, v.w);
    float a0 = __uint_as_float(h0<<16), a1 = __uint_as_float(h0&0xffff0000u);
    float a2 = __uint_as_float(h1<<16), a3 = __uint_as_float(h1&0xffff0000u);
    lo = make_uint2(pk(v.x-a0, v.y-a1), pk(v.z-a2, v.w-a3));
    hi = make_uint2(h0, h1);
}
__device__ __forceinline__ void mma16(float* c, const uint32_t* a, const uint32_t* b){
    asm volatile("mma.sync.aligned.m16n8k16.row.col.f32.bf16.bf16.f32 "
        "{%0,%1,%2,%3},{%4,%5,%6,%7},{%8,%9},{%0,%1,%2,%3};"
        : "+f"(c[0]),"+f"(c[1]),"+f"(c[2]),"+f"(c[3])
        : "r"(a[0]),"r"(a[1]),"r"(a[2]),"r"(a[3]),"r"(b[0]),"r"(b[1]));
}
__device__ __forceinline__ void ldsm4(uint32_t* r, uint32_t addr){
    asm volatile("ldmatrix.sync.aligned.m8n8.x4.shared.b16 {%0,%1,%2,%3}, [%4];"
        : "=r"(r[0]),"=r"(r[1]),"=r"(r[2]),"=r"(r[3]) : "r"(addr));
}
__device__ __forceinline__ void ldsm4t(uint32_t* r, uint32_t addr){
    asm volatile("ldmatrix.sync.aligned.m8n8.x4.trans.shared.b16 {%0,%1,%2,%3}, [%4];"
        : "=r"(r[0]),"=r"(r[1]),"=r"(r[2]),"=r"(r[3]) : "r"(addr));
}

// ---------------------------------------------------------------------------
// Generic batched bf16x2 GEMM, ldmatrix fragment loads, plane smem layout.
// Tile 128x64, BK=32, 8 warps (warp tile 32x32), 2 CTAs/SM.
// ---------------------------------------------------------------------------
template<int BM,int BN,int BK,int WM,int WN,bool TRANSB>
__global__ __launch_bounds__(256,2)
void mma_gemm(const float* __restrict__ A, const float* __restrict__ A2,
              const float* __restrict__ B, float* __restrict__ C,
              const float* __restrict__ bias, const float* __restrict__ resid,
              int K, int lda, int ldb, int ldc,
              int zDiv1, int zDiv2,
              long aS0, long aS1, long aS2,
              long bS0, long bS1, long bS2,
              long cS0, long cS1, long cS2,
              long sS0, long sS1, long sS2,
              float alpha, int relu)
{
    constexpr int BKA = BK + 8;                 // A plane row stride (elems): 40 -> 80B
    constexpr int BNB = BN + 8;                 // B plane row stride (elems): 72 -> 144B
    constexpr int A_PLANE = BM*BKA*2;           // bytes
    constexpr int A_BUF   = 2*A_PLANE;          // hi+lo
    constexpr int B_PLANE = BK*BNB*2;
    constexpr int B_BUF   = 2*B_PLANE;
    constexpr int BUF     = A_BUF + B_BUF;
    constexpr int WCOLS = BN / WN;
    constexpr int MITER = WM/16, NITER = WN/8;
    constexpr int AREG = BM*BK/(256*4);         // 4

    extern __shared__ char smem[];
    const uint32_t sbase = (uint32_t)__cvta_generic_to_shared(smem);

    const int z = blockIdx.z;
    const int i0 = z / zDiv1, rem = z % zDiv1;
    const int i1 = rem / zDiv2, i2 = rem % zDiv2;
    const float* Ap = ((i0==0) ? A : A2) + i0*aS0 + i1*aS1 + i2*aS2;
    const float* Bp = B + i0*bS0 + i1*bS1 + i2*bS2;
    const long cOff = i0*cS0 + i1*cS1 + i2*cS2;
    float* Cp = C + cOff;
    const float* Rp = resid ? resid + cOff : nullptr;
    const float* bp = bias ? bias + i0*sS0 + i1*sS1 + i2*sS2 : nullptr;

    const int row0 = blockIdx.y * BM;
    const int col0 = blockIdx.x * BN;
    const int tid  = threadIdx.x;
    const int lane = tid & 31, w = tid >> 5;
    const int wr = w / WCOLS, wc = w % WCOLS;
    const int g  = lane >> 2, cq = lane & 3;

    // ldmatrix lane addressing (element offsets within planes)
    const int aRow = (lane & 7) + ((lane >> 3) & 1) * 8;   // 0..15
    const int aCol = (lane >> 4) * 8;                      // 0 or 8
    const uint32_t aOffB = ((wr*WM + aRow)*BKA + aCol) * 2;
    const int bRow = lane & 15;
    const int bColOff = (lane >> 4) * 8;
    const uint32_t bOffB = (bRow*BNB + wc*WN + bColOff) * 2;

    float acc[MITER][NITER][4];
    #pragma unroll
    for (int mi=0;mi<MITER;mi++)
        #pragma unroll
        for (int ni=0;ni<NITER;ni++)
            #pragma unroll
            for (int q=0;q<4;q++) acc[mi][ni][q] = 0.f;

    float4 ra[AREG], rb[2];

    auto ldgA = [&](int k0){
        #pragma unroll
        for (int i=0;i<AREG;i++){
            int id = tid + i*256;
            int r = id >> 3, c4 = id & 7;
            ra[i] = *(const float4*)(Ap + (long)(row0+r)*lda + k0 + c4*4);
        }
    };
    auto stsA = [&](int buf){
        char* base = smem + buf*BUF;
        #pragma unroll
        for (int i=0;i<AREG;i++){
            int id = tid + i*256;
            int r = id >> 3, c4 = id & 7;
            uint2 hi, lo; split4(ra[i], hi, lo);
            int off = (r*BKA + c4*4)*2;
            *(uint2*)(base + off)           = hi;
            *(uint2*)(base + A_PLANE + off) = lo;
        }
    };
    auto ldgB = [&](int k0){
        #pragma unroll
        for (int j=0;j<2;j++){
            int id = tid + j*256;
            if (!TRANSB){
                int r = id >> 4, n4 = id & 15;
                rb[j] = *(const float4*)(Bp + (long)(k0+r)*ldb + col0 + n4*4);
            } else {
                int n = id >> 3, kg = id & 7;
                rb[j] = *(const float4*)(Bp + (long)(col0+n)*ldb + k0 + kg*4);
            }
        }
    };
    auto stsB = [&](int buf){
        char* base = smem + buf*BUF + A_BUF;
        #pragma unroll
        for (int j=0;j<2;j++){
            int id = tid + j*256;
            if (!TRANSB){
                int r = id >> 4, n4 = id & 15;
                uint2 hi, lo; split4(rb[j], hi, lo);
                int off = (r*BNB + n4*4)*2;
                *(uint2*)(base + off)           = hi;
                *(uint2*)(base + B_PLANE + off) = lo;
            } else {
                int n = id >> 3, kg = id & 7;
                float v[4] = {rb[j].x, rb[j].y, rb[j].z, rb[j].w};
                #pragma unroll
                for (int e=0;e<4;e++){
                    int k = kg*4 + e;
                    uint32_t h = pk(v[e], 0.f);                 // low half = bf16(v)
                    float hf = __uint_as_float(h << 16);
                    uint32_t l = pk(v[e]-hf, 0.f);
                    int off = (k*BNB + n)*2;
                    *(uint16_t*)(base + off)           = (uint16_t)h;
                    *(uint16_t*)(base + B_PLANE + off) = (uint16_t)l;
                }
            }
        }
    };
    auto compute = [&](int buf){
        const uint32_t aAddr = sbase + buf*BUF + aOffB;
        const uint32_t bAddr = sbase + buf*BUF + A_BUF + bOffB;
        #pragma unroll
        for (int s=0; s<BK/16; s++){
            uint32_t ah[MITER][4], al[MITER][4];
            #pragma unroll
            for (int mi=0; mi<MITER; mi++){
                uint32_t a = aAddr + (mi*16*BKA + s*16)*2;
                ldsm4(ah[mi], a);
                ldsm4(al[mi], a + A_PLANE);
            }
            uint32_t bh[2][4], bl[2][4];
            #pragma unroll
            for (int np=0; np<NITER/2; np++){
                uint32_t b = bAddr + (s*16*BNB + np*16)*2;
                ldsm4t(bh[np], b);
                ldsm4t(bl[np], b + B_PLANE);
            }
            #pragma unroll
            for (int mi=0; mi<MITER; mi++)
                #pragma unroll
                for (int ni=0; ni<NITER; ni++){
                    const uint32_t* bhp = &bh[ni>>1][(ni&1)*2];
                    const uint32_t* blp = &bl[ni>>1][(ni&1)*2];
                    mma16(acc[mi][ni], al[mi], bhp);
                    mma16(acc[mi][ni], ah[mi], blp);
                    mma16(acc[mi][ni], ah[mi], bhp);
                }
        }
    };

    const int nIter = K/BK;
    ldgA(0); ldgB(0);
    stsA(0); stsB(0);
    __syncthreads();
    for (int it=0; it<nIter; ++it){
        if (it+1 < nIter){ ldgA((it+1)*BK); ldgB((it+1)*BK); }
        compute(it & 1);
        if (it+1 < nIter){ stsA((it+1)&1); stsB((it+1)&1); }
        __syncthreads();
    }

    // Epilogue
    #pragma unroll
    for (int mi=0;mi<MITER;mi++){
        #pragma unroll
        for (int ni=0;ni<NITER;ni++){
            int r  = row0 + wr*WM + mi*16 + g;
            int cl = col0 + wc*WN + ni*8 + 2*cq;
            #pragma unroll
            for (int h=0; h<2; h++){
                int rr = r + 8*h;
                float x = acc[mi][ni][2*h  ]*alpha;
                float y = acc[mi][ni][2*h+1]*alpha;
                if (bp){ x += bp[cl]; y += bp[cl+1]; }
                if (Rp){ float2 t = *(const float2*)(Rp + (long)rr*ldc + cl);
                         x += t.x; y += t.y; }
                if (relu){ x = fmaxf(x,0.f); y = fmaxf(y,0.f); }
                *(float2*)(Cp + (long)rr*ldc + cl) = make_float2(x,y);
            }
        }
    }
}

// Shared-memory byte count
template<int BM,int BN,int BK>
constexpr int smemBytes(){
    return 2 * ( 2*BM*(BK+8)*2 + 2*BK*(BN+8)*2 );
}

// ---------------------------------------------------------------------------
// Block reductions (256 threads)
// ---------------------------------------------------------------------------
template<bool IS_MAX>
__device__ __forceinline__ float blockReduce(float v)
{
    __shared__ float sh[8];
    int lane = threadIdx.x & 31, w = threadIdx.x >> 5;
    #pragma unroll
    for (int o=16;o;o>>=1) {
        float u = __shfl_xor_sync(0xffffffffu, v, o);
        v = IS_MAX ? fmaxf(v,u) : v+u;
    }
    if (lane==0) sh[w] = v;
    __syncthreads();
    if (w==0) {
        v = (lane < 8) ? sh[lane] : (IS_MAX ? -__int_as_float(0x7f800000) : 0.f);
        #pragma unroll
        for (int o=4;o;o>>=1) {
            float u = __shfl_xor_sync(0xffffffffu, v, o);
            v = IS_MAX ? fmaxf(v,u) : v+u;
        }
        if (lane==0) sh[0] = v;
    }
    __syncthreads();
    float r = sh[0];
    __syncthreads();
    return r;
}

// ---------------------------------------------------------------------------
// Single-pass softmax: row of T=1024 in registers (float4/thread).
// ---------------------------------------------------------------------------
__global__ __launch_bounds__(256)
void softmax_k(float* __restrict__ s, int causal)
{
    long row = blockIdx.x;
    int t = (int)(row % TT);
    float4* p = (float4*)(s + row * (long)TT);
    int tid = threadIdx.x;
    int base = 4*tid;
    int n = causal ? (t+1) : TT;

    float4 v = p[tid];
    const float NEG = -__int_as_float(0x7f800000);
    if (base+0 >= n) v.x = NEG;
    if (base+1 >= n) v.y = NEG;
    if (base+2 >= n) v.z = NEG;
    if (base+3 >= n) v.w = NEG;

    float mx = fmaxf(fmaxf(v.x,v.y), fmaxf(v.z,v.w));
    mx = blockReduce<true>(mx);

    float4 e;
    e.x = __expf(v.x - mx); e.y = __expf(v.y - mx);
    e.z = __expf(v.z - mx); e.w = __expf(v.w - mx);
    float sum = (e.x + e.y) + (e.z + e.w);
    sum = blockReduce<false>(sum);
    float inv = 1.f / sum;
    e.x *= inv; e.y *= inv; e.z *= inv; e.w *= inv;
    p[tid] = e;
}

// ---------------------------------------------------------------------------
// LayerNorm: rows of C=512
// ---------------------------------------------------------------------------
__global__ __launch_bounds__(256)
void ln_k(const float* __restrict__ x, float* __restrict__ out,
          const float* __restrict__ gamma, const float* __restrict__ beta)
{
    long row = blockIdx.x;
    const float* xr = x + row*(long)CC;
    int tid = threadIdx.x;
    float v0 = xr[tid], v1 = xr[tid+256];
    float mu = blockReduce<false>(v0+v1) * (1.f/CC);
    float d0 = v0-mu, d1 = v1-mu;
    float var = blockReduce<false>(d0*d0 + d1*d1) * (1.f/CC);
    float inv = rsqrtf(var + 1e-5f);
    out[row*(long)CC + tid      ] = d0*inv*gamma[tid]     + beta[tid];
    out[row*(long)CC + tid + 256] = d1*inv*gamma[tid+256] + beta[tid+256];
}

// ---------------------------------------------------------------------------
// Embedding + positional encoding
// ---------------------------------------------------------------------------
__global__ __launch_bounds__(256)
void embed_k(const int* __restrict__ tok, const float* __restrict__ emb,
             float* __restrict__ out)
{
    long idx = (long)blockIdx.x*256 + threadIdx.x;
    if (idx >= (long)BB*TT*CC) return;
    int c = (int)(idx % CC);
    long bt = idx / CC;
    int t = (int)(bt % TT);
    int token = tok[bt];
    const int half = CC/2;
    float pe;
    if (c < half) {
        float rate = powf(10000.f, -(float)c / half);
        pe = sinf((float)t * rate);
    } else {
        float rate = powf(10000.f, -(float)(c-half) / half);
        pe = cosf((float)t * rate);
    }
    out[idx] = emb[(long)token*CC + c] * 22.62741699796952f + pe;  // sqrt(512)
}

// ---------------------------------------------------------------------------
// Host-side launchers
// ---------------------------------------------------------------------------
static void setAttrs()
{
    cudaFuncSetAttribute((const void*)mma_gemm<128,64,32,32,32,false>,
        cudaFuncAttributeMaxDynamicSharedMemorySize, smemBytes<128,64,32>());
    cudaFuncSetAttribute((const void*)mma_gemm<128,64,32,32,32,true>,
        cudaFuncAttributeMaxDynamicSharedMemorySize, smemBytes<128,64,32>());
}

static void gemmP(const float* A, const float* B, float* C,
                  const float* bias, const float* resid,
                  int M, int N, int K, int relu)
{
    dim3 g(N/64, M/128, 1);
    mma_gemm<128,64,32,32,32,false><<<g,256,smemBytes<128,64,32>()>>>(
        A, A, B, C, bias, resid, K, K, N, N,
        1,1, 0,0,0, 0,0,0, 0,0,0, 0,0,0, 1.f, relu);
}

// Full multi-head attention; att gets head-concat output [B*T, C].
static void attention(const float* xq, const float* xkv,
                      const float* wqkv, const float* bqkv,
                      float* qkv, float* s, float* att, int causal)
{
    // Fused QKV projection: z = j*16 + b*8 + h   (j selects A vs A2)
    {
        dim3 g(1, TT/128, 48);
        mma_gemm<128,64,32,32,32,false><<<g,256,smemBytes<128,64,32>()>>>(
            xq, xkv, wqkv, qkv, bqkv, nullptr,
            CC, CC, DD, DD,
            16, 8,
            0, (long)TT*CC, 0,                         // A: b stride
            (long)HH*CC*DD, 0, (long)CC*DD,            // B: j, h strides
            (long)QSZ, (long)HH*TT*DD, (long)TT*DD,    // C: j, b, h
            (long)HH*DD, 0, (long)DD,                  // bias: j, h
            1.f, 0);
    }
    // scores = Q @ K^T * sqrt(D)   (z = b*H+h)
    {
        dim3 g(TT/64, TT/128, BH);
        mma_gemm<128,64,32,32,32,true><<<g,256,smemBytes<128,64,32>()>>>(
            qkv, qkv, qkv + QSZ, s, nullptr, nullptr,
            DD, DD, DD, TT,
            1000000, 1,
            0, (long)TT*DD, 0,
            0, (long)TT*DD, 0,
            0, (long)TT*TT, 0,
            0,0,0,
            8.0f, 0);
    }
    softmax_k<<<BH*TT, 256>>>(s, causal);
    // out = P @ V, written at head-concat position (ldc = C, col offset h*D)
    {
        dim3 g(1, TT/128, BH);
        mma_gemm<128,64,32,32,32,false><<<g,256,smemBytes<128,64,32>()>>>(
            s, s, qkv + 2*QSZ, att, nullptr, nullptr,
            TT, TT, DD, CC,
            1000000, HH,
            0, (long)HH*TT*TT, (long)TT*TT,
            0, (long)HH*TT*DD, (long)TT*DD,
            0, (long)TT*CC, (long)DD,
            0,0,0,
            1.f, 0);
    }
}

extern "C" void kernel_launch(void* const* d_in, const int* in_sizes, int n_in,
                              void* d_out, int out_size)
{
    const int*   src     = (const int*)  d_in[0];
    const int*   tgt     = (const int*)  d_in[1];
    const float* src_emb = (const float*)d_in[2];
    const float* tgt_emb = (const float*)d_in[3];
    const float* e_wqkv  = (const float*)d_in[4];
    const float* e_bqkv  = (const float*)d_in[5];
    const float* e_wo    = (const float*)d_in[6];
    const float* e_bo    = (const float*)d_in[7];
    const float* e_ln1   = (const float*)d_in[8];
    const float* e_ln2   = (const float*)d_in[9];
    const float* e_fw1   = (const float*)d_in[10];
    const float* e_fb1   = (const float*)d_in[11];
    const float* e_fw2   = (const float*)d_in[12];
    const float* e_fb2   = (const float*)d_in[13];
    const float* dsw     = (const float*)d_in[14];
    const float* dsb     = (const float*)d_in[15];
    const float* dw1     = (const float*)d_in[16];
    const float* db1     = (const float*)d_in[17];
    const float* dln1    = (const float*)d_in[18];
    const float* dcw     = (const float*)d_in[19];
    const float* dcb     = (const float*)d_in[20];
    const float* dw2     = (const float*)d_in[21];
    const float* db2     = (const float*)d_in[22];
    const float* dln2    = (const float*)d_in[23];
    const float* dln3    = (const float*)d_in[24];
    const float* dfw1    = (const float*)d_in[25];
    const float* dfb1    = (const float*)d_in[26];
    const float* dfw2    = (const float*)d_in[27];
    const float* dfb2    = (const float*)d_in[28];
    const float* wf      = (const float*)d_in[29];
    const float* bf      = (const float*)d_in[30];
    float* out = (float*)d_out;

    setAttrs();

    float *gx,*gy,*gl,*gq,*gs,*ga,*gf;
    cudaGetSymbolAddress((void**)&gx, g_enc);
    cudaGetSymbolAddress((void**)&gy, g_dec);
    cudaGetSymbolAddress((void**)&gl, g_ln);
    cudaGetSymbolAddress((void**)&gq, g_qkv);
    cudaGetSymbolAddress((void**)&gs, g_s);
    cudaGetSymbolAddress((void**)&ga, g_att);
    cudaGetSymbolAddress((void**)&gf, g_ffn);

    const int embBlocks = (int)(((long)BB*TT*CC + 255) / 256);

    // ---------------- Encoder ----------------
    embed_k<<<embBlocks,256>>>(src, src_emb, gx);
    for (int l=0; l<LL; l++) {
        const float* ln1g = e_ln1 + (long)l*2*CC;
        ln_k<<<M2,256>>>(gx, gl, ln1g, ln1g + CC);
        attention(gl, gl,
                  e_wqkv + (long)l*3*HH*CC*DD, e_bqkv + (long)l*3*HH*DD,
                  gq, gs, ga, 0);
        gemmP(ga, e_wo + (long)l*CC*CC, gx, e_bo + (long)l*CC, gx, M2, CC, CC, 0);
        const float* ln2g = e_ln2 + (long)l*2*CC;
        ln_k<<<M2,256>>>(gx, gl, ln2g, ln2g + CC);
        gemmP(gl, e_fw1 + (long)l*CC*FF, gf, e_fb1 + (long)l*FF, nullptr, M2, FF, CC, 1);
        gemmP(gf, e_fw2 + (long)l*FF*CC, gx, e_fb2 + (long)l*CC, gx, M2, CC, FF, 0);
    }

    // ---------------- Decoder ----------------
    embed_k<<<embBlocks,256>>>(tgt, tgt_emb, gy);
    for (int l=0; l<LL; l++) {
        const float* l1 = dln1 + (long)l*2*CC;
        ln_k<<<M2,256>>>(gy, gl, l1, l1 + CC);
        attention(gl, gl,
                  dsw + (long)l*3*HH*CC*DD, dsb + (long)l*3*HH*DD,
                  gq, gs, ga, 1);                      // causal
        gemmP(ga, dw1 + (long)l*CC*CC, gy, db1 + (long)l*CC, gy, M2, CC, CC, 0);
        const float* l2 = dln2 + (long)l*2*CC;
        ln_k<<<M2,256>>>(gy, gl, l2, l2 + CC);
        attention(gl, gx,                              // cross: kv = enc_out
                  dcw + (long)l*3*HH*CC*DD, dcb + (long)l*3*HH*DD,
                  gq, gs, ga, 0);
        gemmP(ga, dw2 + (long)l*CC*CC, gy, db2 + (long)l*CC, gy, M2, CC, CC, 0);
        const float* l3 = dln3 + (long)l*2*CC;
        ln_k<<<M2,256>>>(gy, gl, l3, l3 + CC);
        gemmP(gl, dfw1 + (long)l*CC*FF, gf, dfb1 + (long)l*FF, nullptr, M2, FF, CC, 1);
        gemmP(gf, dfw2 + (long)l*FF*CC, gy, dfb2 + (long)l*CC, gy, M2, CC, FF, 0);
    }

    // ---------------- Final logits ----------------
    gemmP(gy, wf, out, bf, nullptr, M2, VV, CC, 0);
}